// round 2
// baseline (speedup 1.0000x reference)
#include <cuda_runtime.h>
#include <cuda_bf16.h>

// Problem constants (fixed by the reference setup_inputs)
#define NNODES 50000
#define NEDGES 800000
#define DDIM   128
#define NLAYERS 4

// ---------------- static device scratch (no allocation allowed) ----------------
__device__ float g_X[NNODES * DDIM];     // scaled features / layer input
__device__ float g_AGG[NNODES * DDIM];   // aggregation output
__device__ int   g_outdeg[NNODES];
__device__ int   g_indeg[NNODES];
__device__ float g_ns[NNODES];           // norm_src = clip(outdeg,1)^-0.5
__device__ float g_nd[NNODES];           // norm_dst = clip(indeg,1)^-0.5
__device__ int   g_rowptr[NNODES + 1];
__device__ int   g_cursor[NNODES];
__device__ int   g_col[NEDGES];          // CSR (by dst) column = src node
__device__ int   g_is64;                 // 1 if src/dst are int64, 0 if int32

// Read edge index e from a buffer whose element type is int32 or int64.
__device__ __forceinline__ int edge_idx(const void* p, int e, int is64) {
    if (is64) return (int)((const long long*)p)[e];
    return ((const int*)p)[e];
}

// ---------------- dtype detection (device-side, deterministic) ----------------
__global__ void detect_idx_dtype(const int* src_w, const int* dst_w) {
    // If int64 little-endian with values < 2^31, every odd 32-bit word is 0.
    int bad = 0;
    #pragma unroll
    for (int i = 0; i < 32; i++) {
        bad |= src_w[2 * i + 1];
        bad |= dst_w[2 * i + 1];
    }
    g_is64 = (bad == 0) ? 1 : 0;
}

// ---------------- small utility kernels ----------------
__global__ void zero_ints2(int* a, int* b, int n) {
    int i = blockIdx.x * blockDim.x + threadIdx.x;
    if (i < n) { a[i] = 0; b[i] = 0; }
}

__global__ void count_deg(const void* __restrict__ src,
                          const void* __restrict__ dst,
                          int* outdeg, int* indeg, int E) {
    int e = blockIdx.x * blockDim.x + threadIdx.x;
    int is64 = g_is64;
    if (e < E) {
        atomicAdd(&outdeg[edge_idx(src, e, is64)], 1);
        atomicAdd(&indeg[edge_idx(dst, e, is64)], 1);
    }
}

__global__ void compute_norms(const int* __restrict__ outdeg,
                              const int* __restrict__ indeg,
                              float* ns, float* nd, int n) {
    int i = blockIdx.x * blockDim.x + threadIdx.x;
    if (i < n) {
        ns[i] = rsqrtf((float)(outdeg[i] > 1 ? outdeg[i] : 1));
        nd[i] = rsqrtf((float)(indeg[i]  > 1 ? indeg[i]  : 1));
    }
}

// single-block exclusive scan over counts -> row_ptr (+ cursor copy)
__global__ void scan_kernel(const int* __restrict__ counts,
                            int* row_ptr, int* cursor, int n) {
    __shared__ int part[1024];
    int tid = threadIdx.x;
    int per = (n + 1023) >> 10;
    int s = tid * per;
    int e = s + per; if (e > n) e = n;
    int sum = 0;
    for (int i = s; i < e; i++) sum += counts[i];
    part[tid] = sum;
    __syncthreads();
    // Hillis-Steele inclusive scan
    for (int off = 1; off < 1024; off <<= 1) {
        int v = (tid >= off) ? part[tid - off] : 0;
        __syncthreads();
        part[tid] += v;
        __syncthreads();
    }
    int run = (tid == 0) ? 0 : part[tid - 1];
    for (int i = s; i < e; i++) {
        row_ptr[i] = run;
        cursor[i]  = run;
        run += counts[i];
    }
    if (s < n && e == n) row_ptr[n] = run;  // total
}

__global__ void fill_csr(const void* __restrict__ src,
                         const void* __restrict__ dst,
                         int* cursor, int* col, int E) {
    int e = blockIdx.x * blockDim.x + threadIdx.x;
    int is64 = g_is64;
    if (e < E) {
        int d = edge_idx(dst, e, is64);
        int p = atomicAdd(&cursor[d], 1);
        col[p] = edge_idx(src, e, is64);
    }
}

__global__ void scale_rows(const float* __restrict__ feat,
                           const float* __restrict__ s,
                           float* __restrict__ out, int total) {
    int i = blockIdx.x * blockDim.x + threadIdx.x;
    if (i < total) out[i] = feat[i] * s[i >> 7];
}

// ---------------- aggregation: gather via CSR, warp per node ----------------
__global__ void aggregate(const float* __restrict__ x,
                          const int* __restrict__ row_ptr,
                          const int* __restrict__ col,
                          const float* __restrict__ norm_dst,
                          float* __restrict__ agg, int N) {
    int warp = (blockIdx.x * blockDim.x + threadIdx.x) >> 5;
    int lane = threadIdx.x & 31;
    if (warp >= N) return;
    int beg = row_ptr[warp];
    int end = row_ptr[warp + 1];
    float4 acc = make_float4(0.f, 0.f, 0.f, 0.f);
    for (int e = beg; e < end; e++) {
        int s = __ldg(&col[e]);
        float4 v = *(const float4*)&x[(long)s * DDIM + lane * 4];
        acc.x += v.x; acc.y += v.y; acc.z += v.z; acc.w += v.w;
    }
    float nd = norm_dst[warp];
    acc.x *= nd; acc.y *= nd; acc.z *= nd; acc.w *= nd;
    *(float4*)&agg[(long)warp * DDIM + lane * 4] = acc;
}

// ---------------- GEMM: out = (A @ W + b) * (scale ? scale[row] : 1) ----------------
// A: [N,128], W: [128,128] row-major (k,j), tile 128x128, 256 threads, 8x8/thread
__global__ void gemm_bias(const float* __restrict__ A,
                          const float* __restrict__ W,
                          const float* __restrict__ bias,
                          const float* __restrict__ scale,  // may be nullptr
                          float* __restrict__ out, int N) {
    const int BM = 128, BN = 128, BK = 32;
    __shared__ float sA[BM * BK];   // [row][k]
    __shared__ float sW[BK * BN];   // [k][col]
    int tid = threadIdx.x;          // 256
    int tx = tid & 15;              // column group (cols tx + 16*j)
    int ty = tid >> 4;              // row group   (rows ty*8 + i)
    int row0 = blockIdx.x * BM;

    float acc[8][8];
    #pragma unroll
    for (int i = 0; i < 8; i++)
        #pragma unroll
        for (int j = 0; j < 8; j++) acc[i][j] = 0.f;

    for (int k0 = 0; k0 < DDIM; k0 += BK) {
        // load A tile: 128 rows x 32 k  (1024 float4, 4 per thread)
        #pragma unroll
        for (int it = 0; it < 4; it++) {
            int i = tid + it * 256;
            int r = i >> 3;          // /8 float4 per row
            int c = i & 7;
            int grow = row0 + r;
            float4 v = make_float4(0.f, 0.f, 0.f, 0.f);
            if (grow < N) v = *(const float4*)&A[(long)grow * DDIM + k0 + c * 4];
            *(float4*)&sA[r * BK + c * 4] = v;
        }
        // load W tile: 32 k x 128 cols (1024 float4, 4 per thread)
        #pragma unroll
        for (int it = 0; it < 4; it++) {
            int i = tid + it * 256;
            int r = i >> 5;          // /32 float4 per row
            int c = i & 31;
            *(float4*)&sW[r * BN + c * 4] = *(const float4*)&W[(long)(k0 + r) * DDIM + c * 4];
        }
        __syncthreads();

        #pragma unroll
        for (int kk = 0; kk < BK; kk++) {
            float a[8], w[8];
            #pragma unroll
            for (int i = 0; i < 8; i++) a[i] = sA[(ty * 8 + i) * BK + kk];
            #pragma unroll
            for (int j = 0; j < 8; j++) w[j] = sW[kk * BN + tx + 16 * j];
            #pragma unroll
            for (int i = 0; i < 8; i++)
                #pragma unroll
                for (int j = 0; j < 8; j++)
                    acc[i][j] += a[i] * w[j];
        }
        __syncthreads();
    }

    #pragma unroll
    for (int i = 0; i < 8; i++) {
        int r = row0 + ty * 8 + i;
        if (r < N) {
            float s = scale ? scale[r] : 1.0f;
            #pragma unroll
            for (int j = 0; j < 8; j++) {
                int c = tx + 16 * j;
                out[(long)r * DDIM + c] = (acc[i][j] + bias[c]) * s;
            }
        }
    }
}

// ---------------- launch ----------------
extern "C" void kernel_launch(void* const* d_in, const int* in_sizes, int n_in,
                              void* d_out, int out_size) {
    const float* feat = (const float*)d_in[0];      // [N,128]
    const float* W    = (const float*)d_in[1];      // [4,128,128]
    const float* b    = (const float*)d_in[2];      // [4,128]
    const void*  src  = d_in[3];                    // [E] int32 or int64
    const void*  dst  = d_in[4];                    // [E] int32 or int64
    float* out = (float*)d_out;

    int N = in_sizes[0] / DDIM;
    int E = in_sizes[3];

    float *X, *AGG, *ns, *nd;
    int *outdeg, *indeg, *rowptr, *cursor, *col;
    cudaGetSymbolAddress((void**)&X,      g_X);
    cudaGetSymbolAddress((void**)&AGG,    g_AGG);
    cudaGetSymbolAddress((void**)&ns,     g_ns);
    cudaGetSymbolAddress((void**)&nd,     g_nd);
    cudaGetSymbolAddress((void**)&outdeg, g_outdeg);
    cudaGetSymbolAddress((void**)&indeg,  g_indeg);
    cudaGetSymbolAddress((void**)&rowptr, g_rowptr);
    cudaGetSymbolAddress((void**)&cursor, g_cursor);
    cudaGetSymbolAddress((void**)&col,    g_col);

    // 0) detect index dtype (int32 vs int64) on device
    detect_idx_dtype<<<1, 1>>>((const int*)src, (const int*)dst);

    // 1) degrees + norms
    zero_ints2<<<(N + 255) / 256, 256>>>(outdeg, indeg, N);
    count_deg<<<(E + 255) / 256, 256>>>(src, dst, outdeg, indeg, E);
    compute_norms<<<(N + 255) / 256, 256>>>(outdeg, indeg, ns, nd, N);

    // 2) CSR by dst
    scan_kernel<<<1, 1024>>>(indeg, rowptr, cursor, N);
    fill_csr<<<(E + 255) / 256, 256>>>(src, dst, cursor, col, E);

    // 3) x0 = feat * norm_src
    scale_rows<<<(N * DDIM + 255) / 256, 256>>>(feat, ns, X, N * DDIM);

    // 4) layers
    int agg_blocks  = (N * 32 + 255) / 256;
    int gemm_blocks = (N + 127) / 128;
    for (int l = 0; l < NLAYERS; l++) {
        aggregate<<<agg_blocks, 256>>>(X, rowptr, col, nd, AGG, N);
        const float* Wl = W + (long)l * DDIM * DDIM;
        const float* bl = b + (long)l * DDIM;
        if (l < NLAYERS - 1)
            gemm_bias<<<gemm_blocks, 256>>>(AGG, Wl, bl, ns, X, N);   // fuse next-layer src scaling
        else
            gemm_bias<<<gemm_blocks, 256>>>(AGG, Wl, bl, nullptr, out, N);
    }
}

// round 4
// speedup vs baseline: 1.4459x; 1.4459x over previous
#include <cuda_runtime.h>
#include <cuda_bf16.h>
#include <cstdint>

// Problem constants (fixed by the reference setup_inputs)
#define NNODES 50000
#define NEDGES 800000
#define DDIM   128
#define NLAYERS 4

// ---------------- static device scratch (no allocation allowed) ----------------
__device__ float g_X[NNODES * DDIM];     // layer output
__device__ float g_AGG[NNODES * DDIM];   // aggregation output
__device__ int   g_outdeg[NNODES];
__device__ int   g_indeg[NNODES];
__device__ float g_ns[NNODES];           // norm_src = clip(outdeg,1)^-0.5
__device__ float g_nd[NNODES];           // norm_dst = clip(indeg,1)^-0.5
__device__ int   g_rowptr[NNODES + 1];
__device__ int   g_cursor[NNODES];
__device__ int   g_col[NEDGES];          // CSR (by dst) column = src node
__device__ int   g_is64;                 // 1 if src/dst are int64, 0 if int32
__device__ __nv_bfloat16 g_Wt_hi[NLAYERS * DDIM * DDIM];  // W transposed [n][k], hi part
__device__ __nv_bfloat16 g_Wt_lo[NLAYERS * DDIM * DDIM];  // residual lo part

// ---------------- helpers ----------------
__device__ __forceinline__ uint32_t smem_u32(const void* p) {
    uint32_t a;
    asm("{ .reg .u64 t; cvta.to.shared.u64 t, %1; cvt.u32.u64 %0, t; }" : "=r"(a) : "l"(p));
    return a;
}

__device__ __forceinline__ void ldm_x4(uint32_t& r0, uint32_t& r1, uint32_t& r2, uint32_t& r3,
                                       uint32_t addr) {
    asm volatile("ldmatrix.sync.aligned.m8n8.x4.shared.b16 {%0,%1,%2,%3}, [%4];"
                 : "=r"(r0), "=r"(r1), "=r"(r2), "=r"(r3) : "r"(addr));
}

__device__ __forceinline__ void mma_bf16(float& c0, float& c1, float& c2, float& c3,
                                         uint32_t a0, uint32_t a1, uint32_t a2, uint32_t a3,
                                         uint32_t b0, uint32_t b1) {
    asm volatile("mma.sync.aligned.m16n8k16.row.col.f32.bf16.bf16.f32 "
                 "{%0,%1,%2,%3}, {%4,%5,%6,%7}, {%8,%9}, {%0,%1,%2,%3};"
                 : "+f"(c0), "+f"(c1), "+f"(c2), "+f"(c3)
                 : "r"(a0), "r"(a1), "r"(a2), "r"(a3), "r"(b0), "r"(b1));
}

// Read edge index e from a buffer whose element type is int32 or int64.
__device__ __forceinline__ int edge_idx(const void* p, int e, int is64) {
    if (is64) return (int)((const long long*)p)[e];
    return ((const int*)p)[e];
}

// ---------------- dtype detection (device-side, deterministic) ----------------
__global__ void detect_idx_dtype(const int* src_w, const int* dst_w) {
    int bad = 0;
    #pragma unroll
    for (int i = 0; i < 32; i++) {
        bad |= src_w[2 * i + 1];
        bad |= dst_w[2 * i + 1];
    }
    g_is64 = (bad == 0) ? 1 : 0;
}

// ---------------- small utility kernels ----------------
__global__ void zero_ints2(int* a, int* b, int n) {
    int i = blockIdx.x * blockDim.x + threadIdx.x;
    if (i < n) { a[i] = 0; b[i] = 0; }
}

__global__ void count_deg(const void* __restrict__ src,
                          const void* __restrict__ dst,
                          int* outdeg, int* indeg, int E) {
    int e = blockIdx.x * blockDim.x + threadIdx.x;
    int is64 = g_is64;
    if (e < E) {
        atomicAdd(&outdeg[edge_idx(src, e, is64)], 1);
        atomicAdd(&indeg[edge_idx(dst, e, is64)], 1);
    }
}

__global__ void compute_norms(const int* __restrict__ outdeg,
                              const int* __restrict__ indeg,
                              float* ns, float* nd, int n) {
    int i = blockIdx.x * blockDim.x + threadIdx.x;
    if (i < n) {
        ns[i] = rsqrtf((float)(outdeg[i] > 1 ? outdeg[i] : 1));
        nd[i] = rsqrtf((float)(indeg[i]  > 1 ? indeg[i]  : 1));
    }
}

// single-block exclusive scan over counts -> row_ptr (+ cursor copy)
__global__ void scan_kernel(const int* __restrict__ counts,
                            int* row_ptr, int* cursor, int n) {
    __shared__ int part[1024];
    int tid = threadIdx.x;
    int per = (n + 1023) >> 10;
    int s = tid * per;
    int e = s + per; if (e > n) e = n;
    int sum = 0;
    for (int i = s; i < e; i++) sum += counts[i];
    part[tid] = sum;
    __syncthreads();
    for (int off = 1; off < 1024; off <<= 1) {
        int v = (tid >= off) ? part[tid - off] : 0;
        __syncthreads();
        part[tid] += v;
        __syncthreads();
    }
    int run = (tid == 0) ? 0 : part[tid - 1];
    for (int i = s; i < e; i++) {
        row_ptr[i] = run;
        cursor[i]  = run;
        run += counts[i];
    }
    if (s < n && e == n) row_ptr[n] = run;
}

__global__ void fill_csr(const void* __restrict__ src,
                         const void* __restrict__ dst,
                         int* cursor, int* col, int E) {
    int e = blockIdx.x * blockDim.x + threadIdx.x;
    int is64 = g_is64;
    if (e < E) {
        int d = edge_idx(dst, e, is64);
        int p = atomicAdd(&cursor[d], 1);
        col[p] = edge_idx(src, e, is64);
    }
}

// ---------------- W prep: transpose + bf16 hi/lo split ----------------
__global__ void prep_w(const float* __restrict__ W,
                       __nv_bfloat16* __restrict__ Wh,
                       __nv_bfloat16* __restrict__ Wl) {
    int l = blockIdx.x;
    const float* Ws = W + (long)l * DDIM * DDIM;
    for (int i = threadIdx.x; i < DDIM * DDIM; i += blockDim.x) {
        int n = i >> 7, k = i & 127;
        float x = Ws[k * DDIM + n];                 // transpose: [n][k] = W[k][n]
        __nv_bfloat16 h = __float2bfloat16(x);
        float r = x - __bfloat162float(h);
        Wh[(long)l * DDIM * DDIM + i] = h;
        Wl[(long)l * DDIM * DDIM + i] = __float2bfloat16(r);
    }
}

// ---------------- aggregation: gather via CSR, warp per node, fused norm_src ----------------
__global__ void aggregate(const float* __restrict__ x,
                          const int* __restrict__ row_ptr,
                          const int* __restrict__ col,
                          const float* __restrict__ norm_src,
                          const float* __restrict__ norm_dst,
                          float* __restrict__ agg, int N) {
    int warp = (blockIdx.x * blockDim.x + threadIdx.x) >> 5;
    int lane = threadIdx.x & 31;
    if (warp >= N) return;
    int beg = row_ptr[warp];
    int end = row_ptr[warp + 1];
    float4 acc = make_float4(0.f, 0.f, 0.f, 0.f);
    for (int e = beg; e < end; e++) {
        int s = __ldg(&col[e]);
        float nsv = __ldg(&norm_src[s]);
        float4 v = *(const float4*)&x[(long)s * DDIM + lane * 4];
        acc.x += v.x * nsv; acc.y += v.y * nsv; acc.z += v.z * nsv; acc.w += v.w * nsv;
    }
    float nd = norm_dst[warp];
    acc.x *= nd; acc.y *= nd; acc.z *= nd; acc.w *= nd;
    *(float4*)&agg[(long)warp * DDIM + lane * 4] = acc;
}

// ---------------- tensor-core GEMM via mma.sync (split-bf16, fp32 accum) ----------------
// out[r][n] = sum_k A[r][k] * Wt[n][k] + b[n]
// CTA tile: 128 rows x 128 cols, 8 warps in 2(row)x4(col), warp tile 64x32.
// A staged in smem as bf16 hi/lo with XOR-swizzled 16B chunks (row stride 256B).
// W staged in smem bf16 hi/lo with row stride 272B (conflict-free b-frag lds).

#define SMG_BIAS  0
#define SMG_A_HI  512
#define SMG_A_LO  (SMG_A_HI + 32768)
#define SMG_W_HI  (SMG_A_LO + 32768)
#define SMG_W_LO  (SMG_W_HI + 128 * 272)
#define SMG_TOTAL (SMG_W_LO + 128 * 272)   // 512 + 65536 + 69632 = 135680

__global__ void __launch_bounds__(256) gemm_mma(
    const float* __restrict__ A,
    const __nv_bfloat16* __restrict__ Wt_hi,
    const __nv_bfloat16* __restrict__ Wt_lo,
    const float* __restrict__ bias,
    float* __restrict__ out, int N) {
    extern __shared__ char smem[];
    uint32_t sbase = smem_u32(smem);
    int tid = threadIdx.x;
    int wid = tid >> 5;
    int lane = tid & 31;
    int row0 = blockIdx.x * 128;

    // bias -> smem
    if (tid < DDIM) ((float*)(smem + SMG_BIAS))[tid] = bias[tid];

    // ---- stage A tile (128x128 fp32 -> bf16 hi/lo, swizzled) ----
    #pragma unroll
    for (int i = 0; i < 16; i++) {
        int v = tid + i * 256;            // 4096 float4 loads
        int r = v >> 5;                   // row
        int c = (v & 31) * 4;             // col
        int kc = c >> 3;                  // 16B chunk index (8 bf16)
        uint32_t off = (uint32_t)r * 256u + (uint32_t)((kc ^ (r & 7)) * 16) + (uint32_t)((c & 4) * 2);
        int grow = row0 + r;
        float4 f = make_float4(0.f, 0.f, 0.f, 0.f);
        if (grow < N) f = ((const float4*)A)[(long)grow * 32 + (v & 31)];
        __nv_bfloat16 h0 = __float2bfloat16(f.x), h1 = __float2bfloat16(f.y);
        __nv_bfloat16 h2 = __float2bfloat16(f.z), h3 = __float2bfloat16(f.w);
        __nv_bfloat162 hi01 = {h0, h1}, hi23 = {h2, h3};
        __nv_bfloat162 lo01 = {__float2bfloat16(f.x - __bfloat162float(h0)),
                               __float2bfloat16(f.y - __bfloat162float(h1))};
        __nv_bfloat162 lo23 = {__float2bfloat16(f.z - __bfloat162float(h2)),
                               __float2bfloat16(f.w - __bfloat162float(h3))};
        *(__nv_bfloat162*)(smem + SMG_A_HI + off)     = hi01;
        *(__nv_bfloat162*)(smem + SMG_A_HI + off + 4) = hi23;
        *(__nv_bfloat162*)(smem + SMG_A_LO + off)     = lo01;
        *(__nv_bfloat162*)(smem + SMG_A_LO + off + 4) = lo23;
    }
    // ---- stage W tiles (bf16 [n][k] -> smem, row stride 272B) ----
    #pragma unroll
    for (int i = 0; i < 8; i++) {
        int u = tid + i * 256;            // 2048 16B chunks
        int n = u >> 4;
        int kc = u & 15;
        uint32_t doff = (uint32_t)n * 272u + (uint32_t)kc * 16u;
        *(uint4*)(smem + SMG_W_HI + doff) = ((const uint4*)Wt_hi)[u];
        *(uint4*)(smem + SMG_W_LO + doff) = ((const uint4*)Wt_lo)[u];
    }
    __syncthreads();

    // warp tiling: 2 row-warps x 4 col-warps
    int warpRow = (wid & 1) * 64;         // 4 m16 tiles
    int warpCol = (wid >> 1) * 32;        // 4 n8 tiles

    float c[4][4][4];                     // [mt][nt][reg]
    #pragma unroll
    for (int mt = 0; mt < 4; mt++)
        #pragma unroll
        for (int nt = 0; nt < 4; nt++)
            #pragma unroll
            for (int q = 0; q < 4; q++) c[mt][nt][q] = 0.f;

    // A ldmatrix address components (lane-dependent, k-chunk varying part added in loop)
    int a_r_off = lane & 15;              // row within m16 tile
    int a_kc_half = lane >> 4;            // 0/1 -> second k8 chunk

    #pragma unroll
    for (int kch = 0; kch < 8; kch++) {   // 16 k per chunk
        uint32_t a_hi[4][4], a_lo[4][4];
        #pragma unroll
        for (int mt = 0; mt < 4; mt++) {
            int r = warpRow + mt * 16 + a_r_off;
            int kc = kch * 2 + a_kc_half;
            uint32_t off = (uint32_t)r * 256u + (uint32_t)((kc ^ (r & 7)) * 16);
            ldm_x4(a_hi[mt][0], a_hi[mt][1], a_hi[mt][2], a_hi[mt][3], sbase + SMG_A_HI + off);
            ldm_x4(a_lo[mt][0], a_lo[mt][1], a_lo[mt][2], a_lo[mt][3], sbase + SMG_A_LO + off);
        }
        uint32_t b_hi[4][2], b_lo[4][2];
        #pragma unroll
        for (int nt = 0; nt < 4; nt++) {
            int n = warpCol + nt * 8 + (lane >> 2);
            uint32_t base = (uint32_t)n * 272u + (uint32_t)kch * 32u + (uint32_t)((lane & 3) * 4);
            b_hi[nt][0] = *(const uint32_t*)(smem + SMG_W_HI + base);
            b_hi[nt][1] = *(const uint32_t*)(smem + SMG_W_HI + base + 16);
            b_lo[nt][0] = *(const uint32_t*)(smem + SMG_W_LO + base);
            b_lo[nt][1] = *(const uint32_t*)(smem + SMG_W_LO + base + 16);
        }
        #pragma unroll
        for (int mt = 0; mt < 4; mt++)
            #pragma unroll
            for (int nt = 0; nt < 4; nt++) {
                mma_bf16(c[mt][nt][0], c[mt][nt][1], c[mt][nt][2], c[mt][nt][3],
                         a_hi[mt][0], a_hi[mt][1], a_hi[mt][2], a_hi[mt][3],
                         b_hi[nt][0], b_hi[nt][1]);
                mma_bf16(c[mt][nt][0], c[mt][nt][1], c[mt][nt][2], c[mt][nt][3],
                         a_hi[mt][0], a_hi[mt][1], a_hi[mt][2], a_hi[mt][3],
                         b_lo[nt][0], b_lo[nt][1]);
                mma_bf16(c[mt][nt][0], c[mt][nt][1], c[mt][nt][2], c[mt][nt][3],
                         a_lo[mt][0], a_lo[mt][1], a_lo[mt][2], a_lo[mt][3],
                         b_hi[nt][0], b_hi[nt][1]);
            }
    }

    // ---- epilogue: c + bias -> out ----
    const float* sBias = (const float*)(smem + SMG_BIAS);
    #pragma unroll
    for (int mt = 0; mt < 4; mt++) {
        int r_top = row0 + warpRow + mt * 16 + (lane >> 2);
        int r_bot = r_top + 8;
        #pragma unroll
        for (int nt = 0; nt < 4; nt++) {
            int cn = warpCol + nt * 8 + (lane & 3) * 2;
            float b0 = sBias[cn], b1 = sBias[cn + 1];
            if (r_top < N) {
                float2 o = {c[mt][nt][0] + b0, c[mt][nt][1] + b1};
                *(float2*)&out[(long)r_top * DDIM + cn] = o;
            }
            if (r_bot < N) {
                float2 o = {c[mt][nt][2] + b0, c[mt][nt][3] + b1};
                *(float2*)&out[(long)r_bot * DDIM + cn] = o;
            }
        }
    }
}

// ---------------- launch ----------------
extern "C" void kernel_launch(void* const* d_in, const int* in_sizes, int n_in,
                              void* d_out, int out_size) {
    const float* feat = (const float*)d_in[0];      // [N,128]
    const float* W    = (const float*)d_in[1];      // [4,128,128]
    const float* b    = (const float*)d_in[2];      // [4,128]
    const void*  src  = d_in[3];                    // [E] int32 or int64
    const void*  dst  = d_in[4];                    // [E] int32 or int64
    float* out = (float*)d_out;

    int N = in_sizes[0] / DDIM;
    int E = in_sizes[3];

    float *X, *AGG, *ns, *nd;
    int *outdeg, *indeg, *rowptr, *cursor, *col;
    __nv_bfloat16 *Wth, *Wtl;
    cudaGetSymbolAddress((void**)&X,      g_X);
    cudaGetSymbolAddress((void**)&AGG,    g_AGG);
    cudaGetSymbolAddress((void**)&ns,     g_ns);
    cudaGetSymbolAddress((void**)&nd,     g_nd);
    cudaGetSymbolAddress((void**)&outdeg, g_outdeg);
    cudaGetSymbolAddress((void**)&indeg,  g_indeg);
    cudaGetSymbolAddress((void**)&rowptr, g_rowptr);
    cudaGetSymbolAddress((void**)&cursor, g_cursor);
    cudaGetSymbolAddress((void**)&col,    g_col);
    cudaGetSymbolAddress((void**)&Wth,    g_Wt_hi);
    cudaGetSymbolAddress((void**)&Wtl,    g_Wt_lo);

    static int smem_set = 0;
    if (!smem_set) {
        cudaFuncSetAttribute(gemm_mma, cudaFuncAttributeMaxDynamicSharedMemorySize, SMG_TOTAL);
        smem_set = 1;
    }

    // 0) detect index dtype; prep W splits
    detect_idx_dtype<<<1, 1>>>((const int*)src, (const int*)dst);
    prep_w<<<NLAYERS, 256>>>(W, Wth, Wtl);

    // 1) degrees + norms
    zero_ints2<<<(N + 255) / 256, 256>>>(outdeg, indeg, N);
    count_deg<<<(E + 255) / 256, 256>>>(src, dst, outdeg, indeg, E);
    compute_norms<<<(N + 255) / 256, 256>>>(outdeg, indeg, ns, nd, N);

    // 2) CSR by dst
    scan_kernel<<<1, 1024>>>(indeg, rowptr, cursor, N);
    fill_csr<<<(E + 255) / 256, 256>>>(src, dst, cursor, col, E);

    // 3) layers (norm_src fused into aggregate)
    int agg_blocks  = (N * 32 + 255) / 256;
    int gemm_blocks = (N + 127) / 128;
    for (int l = 0; l < NLAYERS; l++) {
        const float* xin = (l == 0) ? feat : X;
        aggregate<<<agg_blocks, 256>>>(xin, rowptr, col, ns, nd, AGG, N);
        float* yout = (l == NLAYERS - 1) ? out : X;
        gemm_mma<<<gemm_blocks, 256, SMG_TOTAL>>>(
            AGG, Wth + (long)l * DDIM * DDIM, Wtl + (long)l * DDIM * DDIM,
            b + (long)l * DDIM, yout, N);
    }
}

// round 6
// speedup vs baseline: 1.4680x; 1.0153x over previous
#include <cuda_runtime.h>
#include <cuda_bf16.h>
#include <cstdint>

// Problem constants (fixed by the reference setup_inputs)
#define NNODES 50000
#define NEDGES 800000
#define DDIM   128
#define NLAYERS 4

// ---------------- static device scratch (no allocation allowed) ----------------
__device__ float g_X[NNODES * DDIM];     // layer input (pre-scaled by norm_src)
__device__ float g_AGG[NNODES * DDIM];   // aggregation output
__device__ int   g_outdeg[NNODES];
__device__ int   g_indeg[NNODES];
__device__ float g_ns[NNODES];           // norm_src = clip(outdeg,1)^-0.5
__device__ float g_nd[NNODES];           // norm_dst = clip(indeg,1)^-0.5
__device__ int   g_rowptr[NNODES + 1];
__device__ int   g_cursor[NNODES];
__device__ int   g_col[NEDGES];          // CSR (by dst) column = src node
__device__ int   g_is64;                 // 1 if src/dst are int64, 0 if int32
__device__ __nv_bfloat16 g_Wt_hi[NLAYERS * DDIM * DDIM];  // W transposed [n][k], hi part
__device__ __nv_bfloat16 g_Wt_lo[NLAYERS * DDIM * DDIM];  // residual lo part

// ---------------- helpers ----------------
__device__ __forceinline__ uint32_t smem_u32(const void* p) {
    uint32_t a;
    asm("{ .reg .u64 t; cvta.to.shared.u64 t, %1; cvt.u32.u64 %0, t; }" : "=r"(a) : "l"(p));
    return a;
}

__device__ __forceinline__ void ldm_x4(uint32_t& r0, uint32_t& r1, uint32_t& r2, uint32_t& r3,
                                       uint32_t addr) {
    asm volatile("ldmatrix.sync.aligned.m8n8.x4.shared.b16 {%0,%1,%2,%3}, [%4];"
                 : "=r"(r0), "=r"(r1), "=r"(r2), "=r"(r3) : "r"(addr));
}

__device__ __forceinline__ void mma_bf16(float& c0, float& c1, float& c2, float& c3,
                                         uint32_t a0, uint32_t a1, uint32_t a2, uint32_t a3,
                                         uint32_t b0, uint32_t b1) {
    asm volatile("mma.sync.aligned.m16n8k16.row.col.f32.bf16.bf16.f32 "
                 "{%0,%1,%2,%3}, {%4,%5,%6,%7}, {%8,%9}, {%0,%1,%2,%3};"
                 : "+f"(c0), "+f"(c1), "+f"(c2), "+f"(c3)
                 : "r"(a0), "r"(a1), "r"(a2), "r"(a3), "r"(b0), "r"(b1));
}

// Read edge index e from a buffer whose element type is int32 or int64.
__device__ __forceinline__ int edge_idx(const void* p, int e, int is64) {
    if (is64) return (int)((const long long*)p)[e];
    return ((const int*)p)[e];
}

// ---------------- dtype detection (device-side, deterministic) ----------------
__global__ void detect_idx_dtype(const int* src_w, const int* dst_w) {
    int bad = 0;
    #pragma unroll
    for (int i = 0; i < 32; i++) {
        bad |= src_w[2 * i + 1];
        bad |= dst_w[2 * i + 1];
    }
    g_is64 = (bad == 0) ? 1 : 0;
}

// ---------------- small utility kernels ----------------
__global__ void zero_ints2(int* a, int* b, int n) {
    int i = blockIdx.x * blockDim.x + threadIdx.x;
    if (i < n) { a[i] = 0; b[i] = 0; }
}

__global__ void count_deg(const void* __restrict__ src,
                          const void* __restrict__ dst,
                          int* outdeg, int* indeg, int E) {
    int e = blockIdx.x * blockDim.x + threadIdx.x;
    int is64 = g_is64;
    if (e < E) {
        atomicAdd(&outdeg[edge_idx(src, e, is64)], 1);
        atomicAdd(&indeg[edge_idx(dst, e, is64)], 1);
    }
}

__global__ void compute_norms(const int* __restrict__ outdeg,
                              const int* __restrict__ indeg,
                              float* ns, float* nd, int n) {
    int i = blockIdx.x * blockDim.x + threadIdx.x;
    if (i < n) {
        ns[i] = rsqrtf((float)(outdeg[i] > 1 ? outdeg[i] : 1));
        nd[i] = rsqrtf((float)(indeg[i]  > 1 ? indeg[i]  : 1));
    }
}

// single-block exclusive scan over counts -> row_ptr (+ cursor copy)
__global__ void scan_kernel(const int* __restrict__ counts,
                            int* row_ptr, int* cursor, int n) {
    __shared__ int part[1024];
    int tid = threadIdx.x;
    int per = (n + 1023) >> 10;
    int s = tid * per;
    int e = s + per; if (e > n) e = n;
    int sum = 0;
    for (int i = s; i < e; i++) sum += counts[i];
    part[tid] = sum;
    __syncthreads();
    for (int off = 1; off < 1024; off <<= 1) {
        int v = (tid >= off) ? part[tid - off] : 0;
        __syncthreads();
        part[tid] += v;
        __syncthreads();
    }
    int run = (tid == 0) ? 0 : part[tid - 1];
    for (int i = s; i < e; i++) {
        row_ptr[i] = run;
        cursor[i]  = run;
        run += counts[i];
    }
    if (s < n && e == n) row_ptr[n] = run;
}

__global__ void fill_csr(const void* __restrict__ src,
                         const void* __restrict__ dst,
                         int* cursor, int* col, int E) {
    int e = blockIdx.x * blockDim.x + threadIdx.x;
    int is64 = g_is64;
    if (e < E) {
        int d = edge_idx(dst, e, is64);
        int p = atomicAdd(&cursor[d], 1);
        col[p] = edge_idx(src, e, is64);
    }
}

// x0 = feat * norm_src   (layer-0 input pre-scale)
__global__ void scale_rows(const float* __restrict__ feat,
                           const float* __restrict__ s,
                           float* __restrict__ out, int total4) {
    int i = blockIdx.x * blockDim.x + threadIdx.x;
    if (i < total4) {
        float4 v = ((const float4*)feat)[i];
        float sc = s[i >> 5];
        v.x *= sc; v.y *= sc; v.z *= sc; v.w *= sc;
        ((float4*)out)[i] = v;
    }
}

// ---------------- W prep: transpose + bf16 hi/lo split ----------------
__global__ void prep_w(const float* __restrict__ W,
                       __nv_bfloat16* __restrict__ Wh,
                       __nv_bfloat16* __restrict__ Wl) {
    int l = blockIdx.x;
    const float* Ws = W + (long)l * DDIM * DDIM;
    for (int i = threadIdx.x; i < DDIM * DDIM; i += blockDim.x) {
        int n = i >> 7, k = i & 127;
        float x = Ws[k * DDIM + n];                 // transpose: [n][k] = W[k][n]
        __nv_bfloat16 h = __float2bfloat16(x);
        float r = x - __bfloat162float(h);
        Wh[(long)l * DDIM * DDIM + i] = h;
        Wl[(long)l * DDIM * DDIM + i] = __float2bfloat16(r);
    }
}

// ---------------- aggregation: gather via CSR, warp per node, unrolled x4 ----------------
// x is already pre-scaled by norm_src; inner loop is pure float4 sum.
__global__ void aggregate(const float* __restrict__ x,
                          const int* __restrict__ row_ptr,
                          const int* __restrict__ col,
                          const float* __restrict__ norm_dst,
                          float* __restrict__ agg, int N) {
    int warp = (blockIdx.x * blockDim.x + threadIdx.x) >> 5;
    int lane = threadIdx.x & 31;
    if (warp >= N) return;
    int beg = row_ptr[warp];
    int end = row_ptr[warp + 1];
    float4 acc = make_float4(0.f, 0.f, 0.f, 0.f);
    int e = beg;
    for (; e + 4 <= end; e += 4) {
        int s0 = __ldg(&col[e]);
        int s1 = __ldg(&col[e + 1]);
        int s2 = __ldg(&col[e + 2]);
        int s3 = __ldg(&col[e + 3]);
        float4 v0 = *(const float4*)&x[(long)s0 * DDIM + lane * 4];
        float4 v1 = *(const float4*)&x[(long)s1 * DDIM + lane * 4];
        float4 v2 = *(const float4*)&x[(long)s2 * DDIM + lane * 4];
        float4 v3 = *(const float4*)&x[(long)s3 * DDIM + lane * 4];
        acc.x += v0.x; acc.y += v0.y; acc.z += v0.z; acc.w += v0.w;
        acc.x += v1.x; acc.y += v1.y; acc.z += v1.z; acc.w += v1.w;
        acc.x += v2.x; acc.y += v2.y; acc.z += v2.z; acc.w += v2.w;
        acc.x += v3.x; acc.y += v3.y; acc.z += v3.z; acc.w += v3.w;
    }
    for (; e < end; e++) {
        int s = __ldg(&col[e]);
        float4 v = *(const float4*)&x[(long)s * DDIM + lane * 4];
        acc.x += v.x; acc.y += v.y; acc.z += v.z; acc.w += v.w;
    }
    float nd = norm_dst[warp];
    acc.x *= nd; acc.y *= nd; acc.z *= nd; acc.w *= nd;
    *(float4*)&agg[(long)warp * DDIM + lane * 4] = acc;
}

// ---------------- tensor-core GEMM via mma.sync (split-bf16, fp32 accum) ----------------
// out[r][n] = (sum_k A[r][k] * Wt[n][k] + b[n]) * (scale ? scale[r] : 1)
// CTA tile: 128 rows x 128 cols, 8 warps in 2(row)x4(col), warp tile 64x32.

#define SMG_BIAS  0
#define SMG_A_HI  512
#define SMG_A_LO  (SMG_A_HI + 32768)
#define SMG_W_HI  (SMG_A_LO + 32768)
#define SMG_W_LO  (SMG_W_HI + 128 * 272)
#define SMG_TOTAL (SMG_W_LO + 128 * 272)   // 512 + 65536 + 69632 = 135680

__global__ void __launch_bounds__(256) gemm_mma(
    const float* __restrict__ A,
    const __nv_bfloat16* __restrict__ Wt_hi,
    const __nv_bfloat16* __restrict__ Wt_lo,
    const float* __restrict__ bias,
    const float* __restrict__ scale,   // may be nullptr (last layer)
    float* __restrict__ out, int N) {
    extern __shared__ char smem[];
    uint32_t sbase = smem_u32(smem);
    int tid = threadIdx.x;
    int wid = tid >> 5;
    int lane = tid & 31;
    int row0 = blockIdx.x * 128;

    // bias -> smem
    if (tid < DDIM) ((float*)(smem + SMG_BIAS))[tid] = bias[tid];

    // ---- stage A tile (128x128 fp32 -> bf16 hi/lo, swizzled) ----
    #pragma unroll
    for (int i = 0; i < 16; i++) {
        int v = tid + i * 256;            // 4096 float4 loads
        int r = v >> 5;                   // row
        int c = (v & 31) * 4;             // col
        int kc = c >> 3;                  // 16B chunk index (8 bf16)
        uint32_t off = (uint32_t)r * 256u + (uint32_t)((kc ^ (r & 7)) * 16) + (uint32_t)((c & 4) * 2);
        int grow = row0 + r;
        float4 f = make_float4(0.f, 0.f, 0.f, 0.f);
        if (grow < N) f = ((const float4*)A)[(long)grow * 32 + (v & 31)];
        __nv_bfloat16 h0 = __float2bfloat16(f.x), h1 = __float2bfloat16(f.y);
        __nv_bfloat16 h2 = __float2bfloat16(f.z), h3 = __float2bfloat16(f.w);
        __nv_bfloat162 hi01 = {h0, h1}, hi23 = {h2, h3};
        __nv_bfloat162 lo01 = {__float2bfloat16(f.x - __bfloat162float(h0)),
                               __float2bfloat16(f.y - __bfloat162float(h1))};
        __nv_bfloat162 lo23 = {__float2bfloat16(f.z - __bfloat162float(h2)),
                               __float2bfloat16(f.w - __bfloat162float(h3))};
        *(__nv_bfloat162*)(smem + SMG_A_HI + off)     = hi01;
        *(__nv_bfloat162*)(smem + SMG_A_HI + off + 4) = hi23;
        *(__nv_bfloat162*)(smem + SMG_A_LO + off)     = lo01;
        *(__nv_bfloat162*)(smem + SMG_A_LO + off + 4) = lo23;
    }
    // ---- stage W tiles (bf16 [n][k] -> smem, row stride 272B) ----
    #pragma unroll
    for (int i = 0; i < 8; i++) {
        int u = tid + i * 256;            // 2048 16B chunks
        int n = u >> 4;
        int kc = u & 15;
        uint32_t doff = (uint32_t)n * 272u + (uint32_t)kc * 16u;
        *(uint4*)(smem + SMG_W_HI + doff) = ((const uint4*)Wt_hi)[u];
        *(uint4*)(smem + SMG_W_LO + doff) = ((const uint4*)Wt_lo)[u];
    }
    __syncthreads();

    // warp tiling: 2 row-warps x 4 col-warps
    int warpRow = (wid & 1) * 64;         // 4 m16 tiles
    int warpCol = (wid >> 1) * 32;        // 4 n8 tiles

    float c[4][4][4];                     // [mt][nt][reg]
    #pragma unroll
    for (int mt = 0; mt < 4; mt++)
        #pragma unroll
        for (int nt = 0; nt < 4; nt++)
            #pragma unroll
            for (int q = 0; q < 4; q++) c[mt][nt][q] = 0.f;

    int a_r_off = lane & 15;              // row within m16 tile
    int a_kc_half = lane >> 4;            // 0/1 -> second k8 chunk

    #pragma unroll
    for (int kch = 0; kch < 8; kch++) {   // 16 k per chunk
        uint32_t a_hi[4][4], a_lo[4][4];
        #pragma unroll
        for (int mt = 0; mt < 4; mt++) {
            int r = warpRow + mt * 16 + a_r_off;
            int kc = kch * 2 + a_kc_half;
            uint32_t off = (uint32_t)r * 256u + (uint32_t)((kc ^ (r & 7)) * 16);
            ldm_x4(a_hi[mt][0], a_hi[mt][1], a_hi[mt][2], a_hi[mt][3], sbase + SMG_A_HI + off);
            ldm_x4(a_lo[mt][0], a_lo[mt][1], a_lo[mt][2], a_lo[mt][3], sbase + SMG_A_LO + off);
        }
        uint32_t b_hi[4][2], b_lo[4][2];
        #pragma unroll
        for (int nt = 0; nt < 4; nt++) {
            int n = warpCol + nt * 8 + (lane >> 2);
            uint32_t base = (uint32_t)n * 272u + (uint32_t)kch * 32u + (uint32_t)((lane & 3) * 4);
            b_hi[nt][0] = *(const uint32_t*)(smem + SMG_W_HI + base);
            b_hi[nt][1] = *(const uint32_t*)(smem + SMG_W_HI + base + 16);
            b_lo[nt][0] = *(const uint32_t*)(smem + SMG_W_LO + base);
            b_lo[nt][1] = *(const uint32_t*)(smem + SMG_W_LO + base + 16);
        }
        #pragma unroll
        for (int mt = 0; mt < 4; mt++)
            #pragma unroll
            for (int nt = 0; nt < 4; nt++) {
                mma_bf16(c[mt][nt][0], c[mt][nt][1], c[mt][nt][2], c[mt][nt][3],
                         a_hi[mt][0], a_hi[mt][1], a_hi[mt][2], a_hi[mt][3],
                         b_hi[nt][0], b_hi[nt][1]);
                mma_bf16(c[mt][nt][0], c[mt][nt][1], c[mt][nt][2], c[mt][nt][3],
                         a_hi[mt][0], a_hi[mt][1], a_hi[mt][2], a_hi[mt][3],
                         b_lo[nt][0], b_lo[nt][1]);
                mma_bf16(c[mt][nt][0], c[mt][nt][1], c[mt][nt][2], c[mt][nt][3],
                         a_lo[mt][0], a_lo[mt][1], a_lo[mt][2], a_lo[mt][3],
                         b_hi[nt][0], b_hi[nt][1]);
            }
    }

    // ---- epilogue: (c + bias) * scale -> out ----
    const float* sBias = (const float*)(smem + SMG_BIAS);
    #pragma unroll
    for (int mt = 0; mt < 4; mt++) {
        int r_top = row0 + warpRow + mt * 16 + (lane >> 2);
        int r_bot = r_top + 8;
        float s_top = 1.f, s_bot = 1.f;
        if (scale) {
            if (r_top < N) s_top = __ldg(&scale[r_top]);
            if (r_bot < N) s_bot = __ldg(&scale[r_bot]);
        }
        #pragma unroll
        for (int nt = 0; nt < 4; nt++) {
            int cn = warpCol + nt * 8 + (lane & 3) * 2;
            float b0 = sBias[cn], b1 = sBias[cn + 1];
            if (r_top < N) {
                float2 o = {(c[mt][nt][0] + b0) * s_top, (c[mt][nt][1] + b1) * s_top};
                *(float2*)&out[(long)r_top * DDIM + cn] = o;
            }
            if (r_bot < N) {
                float2 o = {(c[mt][nt][2] + b0) * s_bot, (c[mt][nt][3] + b1) * s_bot};
                *(float2*)&out[(long)r_bot * DDIM + cn] = o;
            }
        }
    }
}

// ---------------- launch ----------------
extern "C" void kernel_launch(void* const* d_in, const int* in_sizes, int n_in,
                              void* d_out, int out_size) {
    const float* feat = (const float*)d_in[0];      // [N,128]
    const float* W    = (const float*)d_in[1];      // [4,128,128]
    const float* b    = (const float*)d_in[2];      // [4,128]
    const void*  src  = d_in[3];                    // [E] int32 or int64
    const void*  dst  = d_in[4];                    // [E] int32 or int64
    float* out = (float*)d_out;

    int N = in_sizes[0] / DDIM;
    int E = in_sizes[3];

    float *X, *AGG, *ns, *nd;
    int *outdeg, *indeg, *rowptr, *cursor, *col;
    __nv_bfloat16 *Wth, *Wtl;
    cudaGetSymbolAddress((void**)&X,      g_X);
    cudaGetSymbolAddress((void**)&AGG,    g_AGG);
    cudaGetSymbolAddress((void**)&ns,     g_ns);
    cudaGetSymbolAddress((void**)&nd,     g_nd);
    cudaGetSymbolAddress((void**)&outdeg, g_outdeg);
    cudaGetSymbolAddress((void**)&indeg,  g_indeg);
    cudaGetSymbolAddress((void**)&rowptr, g_rowptr);
    cudaGetSymbolAddress((void**)&cursor, g_cursor);
    cudaGetSymbolAddress((void**)&col,    g_col);
    cudaGetSymbolAddress((void**)&Wth,    g_Wt_hi);
    cudaGetSymbolAddress((void**)&Wtl,    g_Wt_lo);

    static int smem_set = 0;
    if (!smem_set) {
        cudaFuncSetAttribute(gemm_mma, cudaFuncAttributeMaxDynamicSharedMemorySize, SMG_TOTAL);
        smem_set = 1;
    }

    // 0) detect index dtype; prep W splits
    detect_idx_dtype<<<1, 1>>>((const int*)src, (const int*)dst);
    prep_w<<<NLAYERS, 256>>>(W, Wth, Wtl);

    // 1) degrees + norms
    zero_ints2<<<(N + 255) / 256, 256>>>(outdeg, indeg, N);
    count_deg<<<(E + 255) / 256, 256>>>(src, dst, outdeg, indeg, E);
    compute_norms<<<(N + 255) / 256, 256>>>(outdeg, indeg, ns, nd, N);

    // 2) CSR by dst
    scan_kernel<<<1, 1024>>>(indeg, rowptr, cursor, N);
    fill_csr<<<(E + 255) / 256, 256>>>(src, dst, cursor, col, E);

    // 3) layer-0 input pre-scaled by norm_src
    scale_rows<<<(N * 32 + 255) / 256, 256>>>(feat, ns, X, N * 32);

    // 4) layers (norm_src folded into gemm epilogue of layers 0..2)
    int agg_blocks  = (N * 32 + 255) / 256;
    int gemm_blocks = (N + 127) / 128;
    for (int l = 0; l < NLAYERS; l++) {
        aggregate<<<agg_blocks, 256>>>(X, rowptr, col, nd, AGG, N);
        const float* sc = (l == NLAYERS - 1) ? nullptr : ns;
        float* yout = (l == NLAYERS - 1) ? out : X;
        gemm_mma<<<gemm_blocks, 256, SMG_TOTAL>>>(
            AGG, Wth + (long)l * DDIM * DDIM, Wtl + (long)l * DDIM * DDIM,
            b + (long)l * DDIM, sc, yout, N);
    }
}

// round 7
// speedup vs baseline: 1.4725x; 1.0031x over previous
#include <cuda_runtime.h>
#include <cuda_bf16.h>
#include <cstdint>

// Problem constants (fixed by the reference setup_inputs)
#define NNODES 50000
#define NEDGES 800000
#define DDIM   128
#define NLAYERS 4

// ---------------- static device scratch (no allocation allowed) ----------------
__device__ float g_X[NNODES * DDIM];     // layer input (pre-scaled by norm_src)
__device__ float g_AGG[NNODES * DDIM];   // aggregation output
__device__ int   g_outdeg[NNODES];
__device__ int   g_indeg[NNODES];
__device__ float g_ns[NNODES];           // norm_src = clip(outdeg,1)^-0.5
__device__ float g_nd[NNODES];           // norm_dst = clip(indeg,1)^-0.5
__device__ int   g_rowptr[NNODES + 1];
__device__ int   g_cursor[NNODES];
__device__ int   g_col[NEDGES];          // CSR (by dst) column = src node
__device__ int   g_is64;                 // 1 if src/dst are int64, 0 if int32
__device__ __nv_bfloat16 g_Wt_hi[NLAYERS * DDIM * DDIM];  // W transposed [n][k], hi part
__device__ __nv_bfloat16 g_Wt_lo[NLAYERS * DDIM * DDIM];  // residual lo part

// ---------------- helpers ----------------
__device__ __forceinline__ uint32_t smem_u32(const void* p) {
    uint32_t a;
    asm("{ .reg .u64 t; cvta.to.shared.u64 t, %1; cvt.u32.u64 %0, t; }" : "=r"(a) : "l"(p));
    return a;
}

__device__ __forceinline__ void ldm_x4(uint32_t& r0, uint32_t& r1, uint32_t& r2, uint32_t& r3,
                                       uint32_t addr) {
    asm volatile("ldmatrix.sync.aligned.m8n8.x4.shared.b16 {%0,%1,%2,%3}, [%4];"
                 : "=r"(r0), "=r"(r1), "=r"(r2), "=r"(r3) : "r"(addr));
}

__device__ __forceinline__ void mma_bf16(float& c0, float& c1, float& c2, float& c3,
                                         uint32_t a0, uint32_t a1, uint32_t a2, uint32_t a3,
                                         uint32_t b0, uint32_t b1) {
    asm volatile("mma.sync.aligned.m16n8k16.row.col.f32.bf16.bf16.f32 "
                 "{%0,%1,%2,%3}, {%4,%5,%6,%7}, {%8,%9}, {%0,%1,%2,%3};"
                 : "+f"(c0), "+f"(c1), "+f"(c2), "+f"(c3)
                 : "r"(a0), "r"(a1), "r"(a2), "r"(a3), "r"(b0), "r"(b1));
}

// Read edge index e from a buffer whose element type is int32 or int64.
__device__ __forceinline__ int edge_idx(const void* p, int e, int is64) {
    if (is64) return (int)((const long long*)p)[e];
    return ((const int*)p)[e];
}

// ---------------- dtype detection (device-side, deterministic) ----------------
__global__ void detect_idx_dtype(const int* src_w, const int* dst_w) {
    int bad = 0;
    #pragma unroll
    for (int i = 0; i < 32; i++) {
        bad |= src_w[2 * i + 1];
        bad |= dst_w[2 * i + 1];
    }
    g_is64 = (bad == 0) ? 1 : 0;
}

// ---------------- small utility kernels ----------------
__global__ void zero_ints2(int* a, int* b, int n) {
    int i = blockIdx.x * blockDim.x + threadIdx.x;
    if (i < n) { a[i] = 0; b[i] = 0; }
}

__global__ void count_deg(const void* __restrict__ src,
                          const void* __restrict__ dst,
                          int* outdeg, int* indeg, int E) {
    int e = blockIdx.x * blockDim.x + threadIdx.x;
    int is64 = g_is64;
    if (e < E) {
        atomicAdd(&outdeg[edge_idx(src, e, is64)], 1);
        atomicAdd(&indeg[edge_idx(dst, e, is64)], 1);
    }
}

__global__ void compute_norms(const int* __restrict__ outdeg,
                              const int* __restrict__ indeg,
                              float* ns, float* nd, int n) {
    int i = blockIdx.x * blockDim.x + threadIdx.x;
    if (i < n) {
        ns[i] = rsqrtf((float)(outdeg[i] > 1 ? outdeg[i] : 1));
        nd[i] = rsqrtf((float)(indeg[i]  > 1 ? indeg[i]  : 1));
    }
}

// single-block exclusive scan over counts -> row_ptr (+ cursor copy)
__global__ void scan_kernel(const int* __restrict__ counts,
                            int* row_ptr, int* cursor, int n) {
    __shared__ int part[1024];
    int tid = threadIdx.x;
    int per = (n + 1023) >> 10;
    int s = tid * per;
    int e = s + per; if (e > n) e = n;
    int sum = 0;
    for (int i = s; i < e; i++) sum += counts[i];
    part[tid] = sum;
    __syncthreads();
    for (int off = 1; off < 1024; off <<= 1) {
        int v = (tid >= off) ? part[tid - off] : 0;
        __syncthreads();
        part[tid] += v;
        __syncthreads();
    }
    int run = (tid == 0) ? 0 : part[tid - 1];
    for (int i = s; i < e; i++) {
        row_ptr[i] = run;
        cursor[i]  = run;
        run += counts[i];
    }
    if (s < n && e == n) row_ptr[n] = run;
}

__global__ void fill_csr(const void* __restrict__ src,
                         const void* __restrict__ dst,
                         int* cursor, int* col, int E) {
    int e = blockIdx.x * blockDim.x + threadIdx.x;
    int is64 = g_is64;
    if (e < E) {
        int d = edge_idx(dst, e, is64);
        int p = atomicAdd(&cursor[d], 1);
        col[p] = edge_idx(src, e, is64);
    }
}

// x0 = feat * norm_src   (layer-0 input pre-scale)
__global__ void scale_rows(const float* __restrict__ feat,
                           const float* __restrict__ s,
                           float* __restrict__ out, int total4) {
    int i = blockIdx.x * blockDim.x + threadIdx.x;
    if (i < total4) {
        float4 v = ((const float4*)feat)[i];
        float sc = s[i >> 5];
        v.x *= sc; v.y *= sc; v.z *= sc; v.w *= sc;
        ((float4*)out)[i] = v;
    }
}

// ---------------- W prep: transpose + bf16 hi/lo split ----------------
__global__ void prep_w(const float* __restrict__ W,
                       __nv_bfloat16* __restrict__ Wh,
                       __nv_bfloat16* __restrict__ Wl) {
    int l = blockIdx.x;
    const float* Ws = W + (long)l * DDIM * DDIM;
    for (int i = threadIdx.x; i < DDIM * DDIM; i += blockDim.x) {
        int n = i >> 7, k = i & 127;
        float x = Ws[k * DDIM + n];                 // transpose: [n][k] = W[k][n]
        __nv_bfloat16 h = __float2bfloat16(x);
        float r = x - __bfloat162float(h);
        Wh[(long)l * DDIM * DDIM + i] = h;
        Wl[(long)l * DDIM * DDIM + i] = __float2bfloat16(r);
    }
}

// ---------------- aggregation: gather via CSR, warp per node, unrolled x4 ----------------
// x is already pre-scaled by norm_src; inner loop is pure float4 sum.
__global__ void aggregate(const float* __restrict__ x,
                          const int* __restrict__ row_ptr,
                          const int* __restrict__ col,
                          const float* __restrict__ norm_dst,
                          float* __restrict__ agg, int N) {
    int warp = (blockIdx.x * blockDim.x + threadIdx.x) >> 5;
    int lane = threadIdx.x & 31;
    if (warp >= N) return;
    int beg = row_ptr[warp];
    int end = row_ptr[warp + 1];
    float4 acc = make_float4(0.f, 0.f, 0.f, 0.f);
    int e = beg;
    for (; e + 4 <= end; e += 4) {
        int s0 = __ldg(&col[e]);
        int s1 = __ldg(&col[e + 1]);
        int s2 = __ldg(&col[e + 2]);
        int s3 = __ldg(&col[e + 3]);
        float4 v0 = *(const float4*)&x[(long)s0 * DDIM + lane * 4];
        float4 v1 = *(const float4*)&x[(long)s1 * DDIM + lane * 4];
        float4 v2 = *(const float4*)&x[(long)s2 * DDIM + lane * 4];
        float4 v3 = *(const float4*)&x[(long)s3 * DDIM + lane * 4];
        acc.x += v0.x; acc.y += v0.y; acc.z += v0.z; acc.w += v0.w;
        acc.x += v1.x; acc.y += v1.y; acc.z += v1.z; acc.w += v1.w;
        acc.x += v2.x; acc.y += v2.y; acc.z += v2.z; acc.w += v2.w;
        acc.x += v3.x; acc.y += v3.y; acc.z += v3.z; acc.w += v3.w;
    }
    for (; e < end; e++) {
        int s = __ldg(&col[e]);
        float4 v = *(const float4*)&x[(long)s * DDIM + lane * 4];
        acc.x += v.x; acc.y += v.y; acc.z += v.z; acc.w += v.w;
    }
    float nd = norm_dst[warp];
    acc.x *= nd; acc.y *= nd; acc.z *= nd; acc.w *= nd;
    *(float4*)&agg[(long)warp * DDIM + lane * 4] = acc;
}

// ---------------- tensor-core GEMM via mma.sync (split-bf16, fp32 accum) ----------------
// out[r][n] = (sum_k A[r][k] * Wt[n][k] + b[n]) * (scale ? scale[r] : 1)
// CTA tile: 128 rows x 128 cols, 8 warps in 2(row)x4(col), warp tile 64x32.

#define SMG_BIAS  0
#define SMG_A_HI  512
#define SMG_A_LO  (SMG_A_HI + 32768)
#define SMG_W_HI  (SMG_A_LO + 32768)
#define SMG_W_LO  (SMG_W_HI + 128 * 272)
#define SMG_TOTAL (SMG_W_LO + 128 * 272)   // 512 + 65536 + 69632 = 135680

__global__ void __launch_bounds__(256) gemm_mma(
    const float* __restrict__ A,
    const __nv_bfloat16* __restrict__ Wt_hi,
    const __nv_bfloat16* __restrict__ Wt_lo,
    const float* __restrict__ bias,
    const float* __restrict__ scale,   // may be nullptr (last layer)
    float* __restrict__ out, int N) {
    extern __shared__ char smem[];
    uint32_t sbase = smem_u32(smem);
    int tid = threadIdx.x;
    int wid = tid >> 5;
    int lane = tid & 31;
    int row0 = blockIdx.x * 128;

    // bias -> smem
    if (tid < DDIM) ((float*)(smem + SMG_BIAS))[tid] = bias[tid];

    // ---- stage A tile (128x128 fp32 -> bf16 hi/lo, swizzled) ----
    #pragma unroll
    for (int i = 0; i < 16; i++) {
        int v = tid + i * 256;            // 4096 float4 loads
        int r = v >> 5;                   // row
        int c = (v & 31) * 4;             // col
        int kc = c >> 3;                  // 16B chunk index (8 bf16)
        uint32_t off = (uint32_t)r * 256u + (uint32_t)((kc ^ (r & 7)) * 16) + (uint32_t)((c & 4) * 2);
        int grow = row0 + r;
        float4 f = make_float4(0.f, 0.f, 0.f, 0.f);
        if (grow < N) f = ((const float4*)A)[(long)grow * 32 + (v & 31)];
        __nv_bfloat16 h0 = __float2bfloat16(f.x), h1 = __float2bfloat16(f.y);
        __nv_bfloat16 h2 = __float2bfloat16(f.z), h3 = __float2bfloat16(f.w);
        __nv_bfloat162 hi01 = {h0, h1}, hi23 = {h2, h3};
        __nv_bfloat162 lo01 = {__float2bfloat16(f.x - __bfloat162float(h0)),
                               __float2bfloat16(f.y - __bfloat162float(h1))};
        __nv_bfloat162 lo23 = {__float2bfloat16(f.z - __bfloat162float(h2)),
                               __float2bfloat16(f.w - __bfloat162float(h3))};
        *(__nv_bfloat162*)(smem + SMG_A_HI + off)     = hi01;
        *(__nv_bfloat162*)(smem + SMG_A_HI + off + 4) = hi23;
        *(__nv_bfloat162*)(smem + SMG_A_LO + off)     = lo01;
        *(__nv_bfloat162*)(smem + SMG_A_LO + off + 4) = lo23;
    }
    // ---- stage W tiles (bf16 [n][k] -> smem, row stride 272B) ----
    #pragma unroll
    for (int i = 0; i < 8; i++) {
        int u = tid + i * 256;            // 2048 16B chunks
        int n = u >> 4;
        int kc = u & 15;
        uint32_t doff = (uint32_t)n * 272u + (uint32_t)kc * 16u;
        *(uint4*)(smem + SMG_W_HI + doff) = ((const uint4*)Wt_hi)[u];
        *(uint4*)(smem + SMG_W_LO + doff) = ((const uint4*)Wt_lo)[u];
    }
    __syncthreads();

    // warp tiling: 2 row-warps x 4 col-warps
    int warpRow = (wid & 1) * 64;         // 4 m16 tiles
    int warpCol = (wid >> 1) * 32;        // 4 n8 tiles

    float c[4][4][4];                     // [mt][nt][reg]
    #pragma unroll
    for (int mt = 0; mt < 4; mt++)
        #pragma unroll
        for (int nt = 0; nt < 4; nt++)
            #pragma unroll
            for (int q = 0; q < 4; q++) c[mt][nt][q] = 0.f;

    int a_r_off = lane & 15;              // row within m16 tile
    int a_kc_half = lane >> 4;            // 0/1 -> second k8 chunk

    #pragma unroll
    for (int kch = 0; kch < 8; kch++) {   // 16 k per chunk
        uint32_t a_hi[4][4], a_lo[4][4];
        #pragma unroll
        for (int mt = 0; mt < 4; mt++) {
            int r = warpRow + mt * 16 + a_r_off;
            int kc = kch * 2 + a_kc_half;
            uint32_t off = (uint32_t)r * 256u + (uint32_t)((kc ^ (r & 7)) * 16);
            ldm_x4(a_hi[mt][0], a_hi[mt][1], a_hi[mt][2], a_hi[mt][3], sbase + SMG_A_HI + off);
            ldm_x4(a_lo[mt][0], a_lo[mt][1], a_lo[mt][2], a_lo[mt][3], sbase + SMG_A_LO + off);
        }
        uint32_t b_hi[4][2], b_lo[4][2];
        #pragma unroll
        for (int nt = 0; nt < 4; nt++) {
            int n = warpCol + nt * 8 + (lane >> 2);
            uint32_t base = (uint32_t)n * 272u + (uint32_t)kch * 32u + (uint32_t)((lane & 3) * 4);
            b_hi[nt][0] = *(const uint32_t*)(smem + SMG_W_HI + base);
            b_hi[nt][1] = *(const uint32_t*)(smem + SMG_W_HI + base + 16);
            b_lo[nt][0] = *(const uint32_t*)(smem + SMG_W_LO + base);
            b_lo[nt][1] = *(const uint32_t*)(smem + SMG_W_LO + base + 16);
        }
        #pragma unroll
        for (int mt = 0; mt < 4; mt++)
            #pragma unroll
            for (int nt = 0; nt < 4; nt++) {
                mma_bf16(c[mt][nt][0], c[mt][nt][1], c[mt][nt][2], c[mt][nt][3],
                         a_hi[mt][0], a_hi[mt][1], a_hi[mt][2], a_hi[mt][3],
                         b_hi[nt][0], b_hi[nt][1]);
                mma_bf16(c[mt][nt][0], c[mt][nt][1], c[mt][nt][2], c[mt][nt][3],
                         a_hi[mt][0], a_hi[mt][1], a_hi[mt][2], a_hi[mt][3],
                         b_lo[nt][0], b_lo[nt][1]);
                mma_bf16(c[mt][nt][0], c[mt][nt][1], c[mt][nt][2], c[mt][nt][3],
                         a_lo[mt][0], a_lo[mt][1], a_lo[mt][2], a_lo[mt][3],
                         b_hi[nt][0], b_hi[nt][1]);
            }
    }

    // ---- epilogue: (c + bias) * scale -> out ----
    const float* sBias = (const float*)(smem + SMG_BIAS);
    #pragma unroll
    for (int mt = 0; mt < 4; mt++) {
        int r_top = row0 + warpRow + mt * 16 + (lane >> 2);
        int r_bot = r_top + 8;
        float s_top = 1.f, s_bot = 1.f;
        if (scale) {
            if (r_top < N) s_top = __ldg(&scale[r_top]);
            if (r_bot < N) s_bot = __ldg(&scale[r_bot]);
        }
        #pragma unroll
        for (int nt = 0; nt < 4; nt++) {
            int cn = warpCol + nt * 8 + (lane & 3) * 2;
            float b0 = sBias[cn], b1 = sBias[cn + 1];
            if (r_top < N) {
                float2 o = {(c[mt][nt][0] + b0) * s_top, (c[mt][nt][1] + b1) * s_top};
                *(float2*)&out[(long)r_top * DDIM + cn] = o;
            }
            if (r_bot < N) {
                float2 o = {(c[mt][nt][2] + b0) * s_bot, (c[mt][nt][3] + b1) * s_bot};
                *(float2*)&out[(long)r_bot * DDIM + cn] = o;
            }
        }
    }
}

// ---------------- launch ----------------
extern "C" void kernel_launch(void* const* d_in, const int* in_sizes, int n_in,
                              void* d_out, int out_size) {
    const float* feat = (const float*)d_in[0];      // [N,128]
    const float* W    = (const float*)d_in[1];      // [4,128,128]
    const float* b    = (const float*)d_in[2];      // [4,128]
    const void*  src  = d_in[3];                    // [E] int32 or int64
    const void*  dst  = d_in[4];                    // [E] int32 or int64
    float* out = (float*)d_out;

    int N = in_sizes[0] / DDIM;
    int E = in_sizes[3];

    float *X, *AGG, *ns, *nd;
    int *outdeg, *indeg, *rowptr, *cursor, *col;
    __nv_bfloat16 *Wth, *Wtl;
    cudaGetSymbolAddress((void**)&X,      g_X);
    cudaGetSymbolAddress((void**)&AGG,    g_AGG);
    cudaGetSymbolAddress((void**)&ns,     g_ns);
    cudaGetSymbolAddress((void**)&nd,     g_nd);
    cudaGetSymbolAddress((void**)&outdeg, g_outdeg);
    cudaGetSymbolAddress((void**)&indeg,  g_indeg);
    cudaGetSymbolAddress((void**)&rowptr, g_rowptr);
    cudaGetSymbolAddress((void**)&cursor, g_cursor);
    cudaGetSymbolAddress((void**)&col,    g_col);
    cudaGetSymbolAddress((void**)&Wth,    g_Wt_hi);
    cudaGetSymbolAddress((void**)&Wtl,    g_Wt_lo);

    static int smem_set = 0;
    if (!smem_set) {
        cudaFuncSetAttribute(gemm_mma, cudaFuncAttributeMaxDynamicSharedMemorySize, SMG_TOTAL);
        smem_set = 1;
    }

    // 0) detect index dtype; prep W splits
    detect_idx_dtype<<<1, 1>>>((const int*)src, (const int*)dst);
    prep_w<<<NLAYERS, 256>>>(W, Wth, Wtl);

    // 1) degrees + norms
    zero_ints2<<<(N + 255) / 256, 256>>>(outdeg, indeg, N);
    count_deg<<<(E + 255) / 256, 256>>>(src, dst, outdeg, indeg, E);
    compute_norms<<<(N + 255) / 256, 256>>>(outdeg, indeg, ns, nd, N);

    // 2) CSR by dst
    scan_kernel<<<1, 1024>>>(indeg, rowptr, cursor, N);
    fill_csr<<<(E + 255) / 256, 256>>>(src, dst, cursor, col, E);

    // 3) layer-0 input pre-scaled by norm_src
    scale_rows<<<(N * 32 + 255) / 256, 256>>>(feat, ns, X, N * 32);

    // 4) layers (norm_src folded into gemm epilogue of layers 0..2)
    int agg_blocks  = (N * 32 + 255) / 256;
    int gemm_blocks = (N + 127) / 128;
    for (int l = 0; l < NLAYERS; l++) {
        aggregate<<<agg_blocks, 256>>>(X, rowptr, col, nd, AGG, N);
        const float* sc = (l == NLAYERS - 1) ? nullptr : ns;
        float* yout = (l == NLAYERS - 1) ? out : X;
        gemm_mma<<<gemm_blocks, 256, SMG_TOTAL>>>(
            AGG, Wth + (long)l * DDIM * DDIM, Wtl + (long)l * DDIM * DDIM,
            b + (long)l * DDIM, sc, yout, N);
    }
}

// round 8
// speedup vs baseline: 1.5266x; 1.0367x over previous
#include <cuda_runtime.h>
#include <cuda_bf16.h>
#include <cuda_fp16.h>
#include <cstdint>

// Problem constants (fixed by the reference setup_inputs)
#define NNODES 50000
#define NEDGES 800000
#define DDIM   128
#define NLAYERS 4

// ---------------- static device scratch (no allocation allowed) ----------------
__device__ __half g_X[NNODES * DDIM];    // layer input (pre-scaled by norm_src), fp16
__device__ float g_AGG[NNODES * DDIM];   // aggregation output (fp32)
__device__ int   g_outdeg[NNODES];
__device__ int   g_indeg[NNODES];
__device__ float g_ns[NNODES];           // norm_src = clip(outdeg,1)^-0.5
__device__ float g_nd[NNODES];           // norm_dst = clip(indeg,1)^-0.5
__device__ int   g_rowptr[NNODES + 1];
__device__ int   g_cursor[NNODES];
__device__ int   g_col[NEDGES];          // CSR (by dst) column = src node
__device__ int   g_is64;                 // 1 if src/dst are int64, 0 if int32
__device__ __nv_bfloat16 g_Wt_hi[NLAYERS * DDIM * DDIM];  // W transposed [n][k], hi part
__device__ __nv_bfloat16 g_Wt_lo[NLAYERS * DDIM * DDIM];  // residual lo part

// ---------------- helpers ----------------
__device__ __forceinline__ uint32_t smem_u32(const void* p) {
    uint32_t a;
    asm("{ .reg .u64 t; cvta.to.shared.u64 t, %1; cvt.u32.u64 %0, t; }" : "=r"(a) : "l"(p));
    return a;
}

__device__ __forceinline__ void ldm_x4(uint32_t& r0, uint32_t& r1, uint32_t& r2, uint32_t& r3,
                                       uint32_t addr) {
    asm volatile("ldmatrix.sync.aligned.m8n8.x4.shared.b16 {%0,%1,%2,%3}, [%4];"
                 : "=r"(r0), "=r"(r1), "=r"(r2), "=r"(r3) : "r"(addr));
}

__device__ __forceinline__ void mma_bf16(float& c0, float& c1, float& c2, float& c3,
                                         uint32_t a0, uint32_t a1, uint32_t a2, uint32_t a3,
                                         uint32_t b0, uint32_t b1) {
    asm volatile("mma.sync.aligned.m16n8k16.row.col.f32.bf16.bf16.f32 "
                 "{%0,%1,%2,%3}, {%4,%5,%6,%7}, {%8,%9}, {%0,%1,%2,%3};"
                 : "+f"(c0), "+f"(c1), "+f"(c2), "+f"(c3)
                 : "r"(a0), "r"(a1), "r"(a2), "r"(a3), "r"(b0), "r"(b1));
}

// Read edge index e from a buffer whose element type is int32 or int64.
__device__ __forceinline__ int edge_idx(const void* p, int e, int is64) {
    if (is64) return (int)((const long long*)p)[e];
    return ((const int*)p)[e];
}

// ---------------- dtype detection (device-side, deterministic) ----------------
__global__ void detect_idx_dtype(const int* src_w, const int* dst_w) {
    int bad = 0;
    #pragma unroll
    for (int i = 0; i < 32; i++) {
        bad |= src_w[2 * i + 1];
        bad |= dst_w[2 * i + 1];
    }
    g_is64 = (bad == 0) ? 1 : 0;
}

// ---------------- small utility kernels ----------------
__global__ void zero_ints2(int* a, int* b, int n) {
    int i = blockIdx.x * blockDim.x + threadIdx.x;
    if (i < n) { a[i] = 0; b[i] = 0; }
}

__global__ void count_deg(const void* __restrict__ src,
                          const void* __restrict__ dst,
                          int* outdeg, int* indeg, int E) {
    int e = blockIdx.x * blockDim.x + threadIdx.x;
    int is64 = g_is64;
    if (e < E) {
        atomicAdd(&outdeg[edge_idx(src, e, is64)], 1);
        atomicAdd(&indeg[edge_idx(dst, e, is64)], 1);
    }
}

__global__ void compute_norms(const int* __restrict__ outdeg,
                              const int* __restrict__ indeg,
                              float* ns, float* nd, int n) {
    int i = blockIdx.x * blockDim.x + threadIdx.x;
    if (i < n) {
        ns[i] = rsqrtf((float)(outdeg[i] > 1 ? outdeg[i] : 1));
        nd[i] = rsqrtf((float)(indeg[i]  > 1 ? indeg[i]  : 1));
    }
}

// single-block exclusive scan over counts -> row_ptr (+ cursor copy)
__global__ void scan_kernel(const int* __restrict__ counts,
                            int* row_ptr, int* cursor, int n) {
    __shared__ int part[1024];
    int tid = threadIdx.x;
    int per = (n + 1023) >> 10;
    int s = tid * per;
    int e = s + per; if (e > n) e = n;
    int sum = 0;
    for (int i = s; i < e; i++) sum += counts[i];
    part[tid] = sum;
    __syncthreads();
    for (int off = 1; off < 1024; off <<= 1) {
        int v = (tid >= off) ? part[tid - off] : 0;
        __syncthreads();
        part[tid] += v;
        __syncthreads();
    }
    int run = (tid == 0) ? 0 : part[tid - 1];
    for (int i = s; i < e; i++) {
        row_ptr[i] = run;
        cursor[i]  = run;
        run += counts[i];
    }
    if (s < n && e == n) row_ptr[n] = run;
}

__global__ void fill_csr(const void* __restrict__ src,
                         const void* __restrict__ dst,
                         int* cursor, int* col, int E) {
    int e = blockIdx.x * blockDim.x + threadIdx.x;
    int is64 = g_is64;
    if (e < E) {
        int d = edge_idx(dst, e, is64);
        int p = atomicAdd(&cursor[d], 1);
        col[p] = edge_idx(src, e, is64);
    }
}

// x0 = fp16(feat * norm_src)   (layer-0 input pre-scale)
__global__ void scale_rows(const float* __restrict__ feat,
                           const float* __restrict__ s,
                           __half* __restrict__ out, int total4) {
    int i = blockIdx.x * blockDim.x + threadIdx.x;
    if (i < total4) {
        float4 v = ((const float4*)feat)[i];
        float sc = s[i >> 5];
        __half2 h01 = __floats2half2_rn(v.x * sc, v.y * sc);
        __half2 h23 = __floats2half2_rn(v.z * sc, v.w * sc);
        uint2 u = {*(uint32_t*)&h01, *(uint32_t*)&h23};
        ((uint2*)out)[i] = u;
    }
}

// ---------------- W prep: transpose + bf16 hi/lo split ----------------
__global__ void prep_w(const float* __restrict__ W,
                       __nv_bfloat16* __restrict__ Wh,
                       __nv_bfloat16* __restrict__ Wl) {
    int l = blockIdx.x;
    const float* Ws = W + (long)l * DDIM * DDIM;
    for (int i = threadIdx.x; i < DDIM * DDIM; i += blockDim.x) {
        int n = i >> 7, k = i & 127;
        float x = Ws[k * DDIM + n];                 // transpose: [n][k] = W[k][n]
        __nv_bfloat16 h = __float2bfloat16(x);
        float r = x - __bfloat162float(h);
        Wh[(long)l * DDIM * DDIM + i] = h;
        Wl[(long)l * DDIM * DDIM + i] = __float2bfloat16(r);
    }
}

// ---------------- aggregation: gather fp16 rows via CSR, warp per node ----------------
// x is fp16, pre-scaled by norm_src; accumulate in fp32.
__device__ __forceinline__ void acc_row(float4& acc, uint2 u) {
    float2 f0 = __half22float2(*(__half2*)&u.x);
    float2 f1 = __half22float2(*(__half2*)&u.y);
    acc.x += f0.x; acc.y += f0.y; acc.z += f1.x; acc.w += f1.y;
}

__global__ void aggregate(const __half* __restrict__ x,
                          const int* __restrict__ row_ptr,
                          const int* __restrict__ col,
                          const float* __restrict__ norm_dst,
                          float* __restrict__ agg, int N) {
    int warp = (blockIdx.x * blockDim.x + threadIdx.x) >> 5;
    int lane = threadIdx.x & 31;
    if (warp >= N) return;
    int beg = row_ptr[warp];
    int end = row_ptr[warp + 1];
    float4 acc = make_float4(0.f, 0.f, 0.f, 0.f);
    int e = beg;
    for (; e + 4 <= end; e += 4) {
        int s0 = __ldg(&col[e]);
        int s1 = __ldg(&col[e + 1]);
        int s2 = __ldg(&col[e + 2]);
        int s3 = __ldg(&col[e + 3]);
        uint2 u0 = *(const uint2*)&x[(long)s0 * DDIM + lane * 4];
        uint2 u1 = *(const uint2*)&x[(long)s1 * DDIM + lane * 4];
        uint2 u2 = *(const uint2*)&x[(long)s2 * DDIM + lane * 4];
        uint2 u3 = *(const uint2*)&x[(long)s3 * DDIM + lane * 4];
        acc_row(acc, u0); acc_row(acc, u1); acc_row(acc, u2); acc_row(acc, u3);
    }
    for (; e < end; e++) {
        int s = __ldg(&col[e]);
        uint2 u = *(const uint2*)&x[(long)s * DDIM + lane * 4];
        acc_row(acc, u);
    }
    float nd = norm_dst[warp];
    acc.x *= nd; acc.y *= nd; acc.z *= nd; acc.w *= nd;
    *(float4*)&agg[(long)warp * DDIM + lane * 4] = acc;
}

// ---------------- tensor-core GEMM via mma.sync (split-bf16, fp32 accum) ----------------
// y = A @ Wt^T + b ;  if out_h: out_h = fp16(y * scale[row]) (next-layer input)
//                     else:     out_f = y (final fp32 output)
// CTA tile: 128 rows x 128 cols, 8 warps in 2(row)x4(col), warp tile 64x32.

#define SMG_BIAS  0
#define SMG_A_HI  512
#define SMG_A_LO  (SMG_A_HI + 32768)
#define SMG_W_HI  (SMG_A_LO + 32768)
#define SMG_W_LO  (SMG_W_HI + 128 * 272)
#define SMG_TOTAL (SMG_W_LO + 128 * 272)   // 512 + 65536 + 69632 = 135680

__global__ void __launch_bounds__(256) gemm_mma(
    const float* __restrict__ A,
    const __nv_bfloat16* __restrict__ Wt_hi,
    const __nv_bfloat16* __restrict__ Wt_lo,
    const float* __restrict__ bias,
    const float* __restrict__ scale,   // used only when out_h != nullptr
    __half* __restrict__ out_h,        // fp16 output (layers 0..2)
    float* __restrict__ out_f,         // fp32 output (last layer)
    int N) {
    extern __shared__ char smem[];
    uint32_t sbase = smem_u32(smem);
    int tid = threadIdx.x;
    int wid = tid >> 5;
    int lane = tid & 31;
    int row0 = blockIdx.x * 128;

    // bias -> smem
    if (tid < DDIM) ((float*)(smem + SMG_BIAS))[tid] = bias[tid];

    // ---- stage A tile (128x128 fp32 -> bf16 hi/lo, swizzled) ----
    #pragma unroll
    for (int i = 0; i < 16; i++) {
        int v = tid + i * 256;            // 4096 float4 loads
        int r = v >> 5;                   // row
        int c = (v & 31) * 4;             // col
        int kc = c >> 3;                  // 16B chunk index (8 bf16)
        uint32_t off = (uint32_t)r * 256u + (uint32_t)((kc ^ (r & 7)) * 16) + (uint32_t)((c & 4) * 2);
        int grow = row0 + r;
        float4 f = make_float4(0.f, 0.f, 0.f, 0.f);
        if (grow < N) f = ((const float4*)A)[(long)grow * 32 + (v & 31)];
        __nv_bfloat16 h0 = __float2bfloat16(f.x), h1 = __float2bfloat16(f.y);
        __nv_bfloat16 h2 = __float2bfloat16(f.z), h3 = __float2bfloat16(f.w);
        __nv_bfloat162 hi01 = {h0, h1}, hi23 = {h2, h3};
        __nv_bfloat162 lo01 = {__float2bfloat16(f.x - __bfloat162float(h0)),
                               __float2bfloat16(f.y - __bfloat162float(h1))};
        __nv_bfloat162 lo23 = {__float2bfloat16(f.z - __bfloat162float(h2)),
                               __float2bfloat16(f.w - __bfloat162float(h3))};
        *(__nv_bfloat162*)(smem + SMG_A_HI + off)     = hi01;
        *(__nv_bfloat162*)(smem + SMG_A_HI + off + 4) = hi23;
        *(__nv_bfloat162*)(smem + SMG_A_LO + off)     = lo01;
        *(__nv_bfloat162*)(smem + SMG_A_LO + off + 4) = lo23;
    }
    // ---- stage W tiles (bf16 [n][k] -> smem, row stride 272B) ----
    #pragma unroll
    for (int i = 0; i < 8; i++) {
        int u = tid + i * 256;            // 2048 16B chunks
        int n = u >> 4;
        int kc = u & 15;
        uint32_t doff = (uint32_t)n * 272u + (uint32_t)kc * 16u;
        *(uint4*)(smem + SMG_W_HI + doff) = ((const uint4*)Wt_hi)[u];
        *(uint4*)(smem + SMG_W_LO + doff) = ((const uint4*)Wt_lo)[u];
    }
    __syncthreads();

    // warp tiling: 2 row-warps x 4 col-warps
    int warpRow = (wid & 1) * 64;         // 4 m16 tiles
    int warpCol = (wid >> 1) * 32;        // 4 n8 tiles

    float c[4][4][4];                     // [mt][nt][reg]
    #pragma unroll
    for (int mt = 0; mt < 4; mt++)
        #pragma unroll
        for (int nt = 0; nt < 4; nt++)
            #pragma unroll
            for (int q = 0; q < 4; q++) c[mt][nt][q] = 0.f;

    int a_r_off = lane & 15;              // row within m16 tile
    int a_kc_half = lane >> 4;            // 0/1 -> second k8 chunk

    #pragma unroll
    for (int kch = 0; kch < 8; kch++) {   // 16 k per chunk
        uint32_t a_hi[4][4], a_lo[4][4];
        #pragma unroll
        for (int mt = 0; mt < 4; mt++) {
            int r = warpRow + mt * 16 + a_r_off;
            int kc = kch * 2 + a_kc_half;
            uint32_t off = (uint32_t)r * 256u + (uint32_t)((kc ^ (r & 7)) * 16);
            ldm_x4(a_hi[mt][0], a_hi[mt][1], a_hi[mt][2], a_hi[mt][3], sbase + SMG_A_HI + off);
            ldm_x4(a_lo[mt][0], a_lo[mt][1], a_lo[mt][2], a_lo[mt][3], sbase + SMG_A_LO + off);
        }
        uint32_t b_hi[4][2], b_lo[4][2];
        #pragma unroll
        for (int nt = 0; nt < 4; nt++) {
            int n = warpCol + nt * 8 + (lane >> 2);
            uint32_t base = (uint32_t)n * 272u + (uint32_t)kch * 32u + (uint32_t)((lane & 3) * 4);
            b_hi[nt][0] = *(const uint32_t*)(smem + SMG_W_HI + base);
            b_hi[nt][1] = *(const uint32_t*)(smem + SMG_W_HI + base + 16);
            b_lo[nt][0] = *(const uint32_t*)(smem + SMG_W_LO + base);
            b_lo[nt][1] = *(const uint32_t*)(smem + SMG_W_LO + base + 16);
        }
        #pragma unroll
        for (int mt = 0; mt < 4; mt++)
            #pragma unroll
            for (int nt = 0; nt < 4; nt++) {
                mma_bf16(c[mt][nt][0], c[mt][nt][1], c[mt][nt][2], c[mt][nt][3],
                         a_hi[mt][0], a_hi[mt][1], a_hi[mt][2], a_hi[mt][3],
                         b_hi[nt][0], b_hi[nt][1]);
                mma_bf16(c[mt][nt][0], c[mt][nt][1], c[mt][nt][2], c[mt][nt][3],
                         a_hi[mt][0], a_hi[mt][1], a_hi[mt][2], a_hi[mt][3],
                         b_lo[nt][0], b_lo[nt][1]);
                mma_bf16(c[mt][nt][0], c[mt][nt][1], c[mt][nt][2], c[mt][nt][3],
                         a_lo[mt][0], a_lo[mt][1], a_lo[mt][2], a_lo[mt][3],
                         b_hi[nt][0], b_hi[nt][1]);
            }
    }

    // ---- epilogue ----
    const float* sBias = (const float*)(smem + SMG_BIAS);
    #pragma unroll
    for (int mt = 0; mt < 4; mt++) {
        int r_top = row0 + warpRow + mt * 16 + (lane >> 2);
        int r_bot = r_top + 8;
        float s_top = 1.f, s_bot = 1.f;
        if (out_h) {
            if (r_top < N) s_top = __ldg(&scale[r_top]);
            if (r_bot < N) s_bot = __ldg(&scale[r_bot]);
        }
        #pragma unroll
        for (int nt = 0; nt < 4; nt++) {
            int cn = warpCol + nt * 8 + (lane & 3) * 2;
            float b0 = sBias[cn], b1 = sBias[cn + 1];
            if (out_h) {
                if (r_top < N) {
                    __half2 h = __floats2half2_rn((c[mt][nt][0] + b0) * s_top,
                                                  (c[mt][nt][1] + b1) * s_top);
                    *(__half2*)&out_h[(long)r_top * DDIM + cn] = h;
                }
                if (r_bot < N) {
                    __half2 h = __floats2half2_rn((c[mt][nt][2] + b0) * s_bot,
                                                  (c[mt][nt][3] + b1) * s_bot);
                    *(__half2*)&out_h[(long)r_bot * DDIM + cn] = h;
                }
            } else {
                if (r_top < N) {
                    float2 o = {c[mt][nt][0] + b0, c[mt][nt][1] + b1};
                    *(float2*)&out_f[(long)r_top * DDIM + cn] = o;
                }
                if (r_bot < N) {
                    float2 o = {c[mt][nt][2] + b0, c[mt][nt][3] + b1};
                    *(float2*)&out_f[(long)r_bot * DDIM + cn] = o;
                }
            }
        }
    }
}

// ---------------- launch ----------------
extern "C" void kernel_launch(void* const* d_in, const int* in_sizes, int n_in,
                              void* d_out, int out_size) {
    const float* feat = (const float*)d_in[0];      // [N,128]
    const float* W    = (const float*)d_in[1];      // [4,128,128]
    const float* b    = (const float*)d_in[2];      // [4,128]
    const void*  src  = d_in[3];                    // [E] int32 or int64
    const void*  dst  = d_in[4];                    // [E] int32 or int64
    float* out = (float*)d_out;

    int N = in_sizes[0] / DDIM;
    int E = in_sizes[3];

    float *AGG, *ns, *nd;
    __half* X;
    int *outdeg, *indeg, *rowptr, *cursor, *col;
    __nv_bfloat16 *Wth, *Wtl;
    cudaGetSymbolAddress((void**)&X,      g_X);
    cudaGetSymbolAddress((void**)&AGG,    g_AGG);
    cudaGetSymbolAddress((void**)&ns,     g_ns);
    cudaGetSymbolAddress((void**)&nd,     g_nd);
    cudaGetSymbolAddress((void**)&outdeg, g_outdeg);
    cudaGetSymbolAddress((void**)&indeg,  g_indeg);
    cudaGetSymbolAddress((void**)&rowptr, g_rowptr);
    cudaGetSymbolAddress((void**)&cursor, g_cursor);
    cudaGetSymbolAddress((void**)&col,    g_col);
    cudaGetSymbolAddress((void**)&Wth,    g_Wt_hi);
    cudaGetSymbolAddress((void**)&Wtl,    g_Wt_lo);

    static int smem_set = 0;
    if (!smem_set) {
        cudaFuncSetAttribute(gemm_mma, cudaFuncAttributeMaxDynamicSharedMemorySize, SMG_TOTAL);
        smem_set = 1;
    }

    // 0) detect index dtype; prep W splits
    detect_idx_dtype<<<1, 1>>>((const int*)src, (const int*)dst);
    prep_w<<<NLAYERS, 256>>>(W, Wth, Wtl);

    // 1) degrees + norms
    zero_ints2<<<(N + 255) / 256, 256>>>(outdeg, indeg, N);
    count_deg<<<(E + 255) / 256, 256>>>(src, dst, outdeg, indeg, E);
    compute_norms<<<(N + 255) / 256, 256>>>(outdeg, indeg, ns, nd, N);

    // 2) CSR by dst
    scan_kernel<<<1, 1024>>>(indeg, rowptr, cursor, N);
    fill_csr<<<(E + 255) / 256, 256>>>(src, dst, cursor, col, E);

    // 3) layer-0 input: fp16(feat * norm_src)
    scale_rows<<<(N * 32 + 255) / 256, 256>>>(feat, ns, X, N * 32);

    // 4) layers (norm_src folded into gemm epilogue of layers 0..2)
    int agg_blocks  = (N * 32 + 255) / 256;
    int gemm_blocks = (N + 127) / 128;
    for (int l = 0; l < NLAYERS; l++) {
        aggregate<<<agg_blocks, 256>>>(X, rowptr, col, nd, AGG, N);
        bool last = (l == NLAYERS - 1);
        gemm_mma<<<gemm_blocks, 256, SMG_TOTAL>>>(
            AGG, Wth + (long)l * DDIM * DDIM, Wtl + (long)l * DDIM * DDIM,
            b + (long)l * DDIM, ns,
            last ? nullptr : X, last ? out : nullptr, N);
    }
}

// round 9
// speedup vs baseline: 1.5405x; 1.0091x over previous
#include <cuda_runtime.h>
#include <cuda_bf16.h>
#include <cuda_fp16.h>
#include <cstdint>

// Problem constants (fixed by the reference setup_inputs)
#define NNODES 50000
#define NEDGES 800000
#define DDIM   128
#define NLAYERS 4

// ---------------- static device scratch (no allocation allowed) ----------------
__device__ __half g_X[NNODES * DDIM];    // layer input (pre-scaled by norm_src), fp16
__device__ float g_AGG[NNODES * DDIM];   // aggregation output (fp32)
__device__ int   g_outdeg[NNODES];
__device__ int   g_indeg[NNODES];
__device__ float g_ns[NNODES];           // norm_src = clip(outdeg,1)^-0.5
__device__ float g_nd[NNODES];           // norm_dst = clip(indeg,1)^-0.5
__device__ int   g_rowptr[NNODES + 1];
__device__ int   g_cursor[NNODES];
__device__ int   g_col[NEDGES];          // CSR (by dst) column = src node
__device__ int   g_is64;                 // 1 if src/dst are int64, 0 if int32
__device__ __nv_bfloat16 g_Wt_hi[NLAYERS * DDIM * DDIM];  // W transposed [n][k], hi part
__device__ __nv_bfloat16 g_Wt_lo[NLAYERS * DDIM * DDIM];  // residual lo part

// ---------------- helpers ----------------
__device__ __forceinline__ uint32_t smem_u32(const void* p) {
    uint32_t a;
    asm("{ .reg .u64 t; cvta.to.shared.u64 t, %1; cvt.u32.u64 %0, t; }" : "=r"(a) : "l"(p));
    return a;
}

__device__ __forceinline__ void ldm_x4(uint32_t& r0, uint32_t& r1, uint32_t& r2, uint32_t& r3,
                                       uint32_t addr) {
    asm volatile("ldmatrix.sync.aligned.m8n8.x4.shared.b16 {%0,%1,%2,%3}, [%4];"
                 : "=r"(r0), "=r"(r1), "=r"(r2), "=r"(r3) : "r"(addr));
}

__device__ __forceinline__ void mma_bf16(float& c0, float& c1, float& c2, float& c3,
                                         uint32_t a0, uint32_t a1, uint32_t a2, uint32_t a3,
                                         uint32_t b0, uint32_t b1) {
    asm volatile("mma.sync.aligned.m16n8k16.row.col.f32.bf16.bf16.f32 "
                 "{%0,%1,%2,%3}, {%4,%5,%6,%7}, {%8,%9}, {%0,%1,%2,%3};"
                 : "+f"(c0), "+f"(c1), "+f"(c2), "+f"(c3)
                 : "r"(a0), "r"(a1), "r"(a2), "r"(a3), "r"(b0), "r"(b1));
}

// Read edge index e from a buffer whose element type is int32 or int64.
__device__ __forceinline__ int edge_idx(const void* p, int e, int is64) {
    if (is64) return (int)((const long long*)p)[e];
    return ((const int*)p)[e];
}

// ---------------- dtype detection (device-side, deterministic) ----------------
__global__ void detect_idx_dtype(const int* src_w, const int* dst_w) {
    int bad = 0;
    #pragma unroll
    for (int i = 0; i < 32; i++) {
        bad |= src_w[2 * i + 1];
        bad |= dst_w[2 * i + 1];
    }
    g_is64 = (bad == 0) ? 1 : 0;
}

// ---------------- small utility kernels ----------------
__global__ void zero_ints2(int* a, int* b, int n) {
    int i = blockIdx.x * blockDim.x + threadIdx.x;
    if (i < n) { a[i] = 0; b[i] = 0; }
}

__global__ void count_deg(const void* __restrict__ src,
                          const void* __restrict__ dst,
                          int* outdeg, int* indeg, int E) {
    int e = blockIdx.x * blockDim.x + threadIdx.x;
    int is64 = g_is64;
    if (e < E) {
        atomicAdd(&outdeg[edge_idx(src, e, is64)], 1);
        atomicAdd(&indeg[edge_idx(dst, e, is64)], 1);
    }
}

__global__ void compute_norms(const int* __restrict__ outdeg,
                              const int* __restrict__ indeg,
                              float* ns, float* nd, int n) {
    int i = blockIdx.x * blockDim.x + threadIdx.x;
    if (i < n) {
        ns[i] = rsqrtf((float)(outdeg[i] > 1 ? outdeg[i] : 1));
        nd[i] = rsqrtf((float)(indeg[i]  > 1 ? indeg[i]  : 1));
    }
}

// single-block exclusive scan over counts -> row_ptr (+ cursor copy)
__global__ void scan_kernel(const int* __restrict__ counts,
                            int* row_ptr, int* cursor, int n) {
    __shared__ int part[1024];
    int tid = threadIdx.x;
    int per = (n + 1023) >> 10;
    int s = tid * per;
    int e = s + per; if (e > n) e = n;
    int sum = 0;
    for (int i = s; i < e; i++) sum += counts[i];
    part[tid] = sum;
    __syncthreads();
    for (int off = 1; off < 1024; off <<= 1) {
        int v = (tid >= off) ? part[tid - off] : 0;
        __syncthreads();
        part[tid] += v;
        __syncthreads();
    }
    int run = (tid == 0) ? 0 : part[tid - 1];
    for (int i = s; i < e; i++) {
        row_ptr[i] = run;
        cursor[i]  = run;
        run += counts[i];
    }
    if (s < n && e == n) row_ptr[n] = run;
}

__global__ void fill_csr(const void* __restrict__ src,
                         const void* __restrict__ dst,
                         int* cursor, int* col, int E) {
    int e = blockIdx.x * blockDim.x + threadIdx.x;
    int is64 = g_is64;
    if (e < E) {
        int d = edge_idx(dst, e, is64);
        int p = atomicAdd(&cursor[d], 1);
        col[p] = edge_idx(src, e, is64);
    }
}

// x0 = fp16(feat * norm_src)   (layer-0 input pre-scale)
__global__ void scale_rows(const float* __restrict__ feat,
                           const float* __restrict__ s,
                           __half* __restrict__ out, int total4) {
    int i = blockIdx.x * blockDim.x + threadIdx.x;
    if (i < total4) {
        float4 v = ((const float4*)feat)[i];
        float sc = s[i >> 5];
        __half2 h01 = __floats2half2_rn(v.x * sc, v.y * sc);
        __half2 h23 = __floats2half2_rn(v.z * sc, v.w * sc);
        uint2 u = {*(uint32_t*)&h01, *(uint32_t*)&h23};
        ((uint2*)out)[i] = u;
    }
}

// ---------------- W prep: transpose + bf16 hi/lo split ----------------
__global__ void prep_w(const float* __restrict__ W,
                       __nv_bfloat16* __restrict__ Wh,
                       __nv_bfloat16* __restrict__ Wl) {
    int l = blockIdx.x;
    const float* Ws = W + (long)l * DDIM * DDIM;
    for (int i = threadIdx.x; i < DDIM * DDIM; i += blockDim.x) {
        int n = i >> 7, k = i & 127;
        float x = Ws[k * DDIM + n];                 // transpose: [n][k] = W[k][n]
        __nv_bfloat16 h = __float2bfloat16(x);
        float r = x - __bfloat162float(h);
        Wh[(long)l * DDIM * DDIM + i] = h;
        Wl[(long)l * DDIM * DDIM + i] = __float2bfloat16(r);
    }
}

// ---------------- aggregation: warp/node, coalesced index preload + shuffle ----------------
// x is fp16, pre-scaled by norm_src; accumulate in fp32.
// Lane l preloads col[base+l] in ONE coalesced LDG, then indices are broadcast
// via shfl — the per-edge gathers have no memory-dependent address chain and
// up to 32 row-gathers are in flight per warp.
__device__ __forceinline__ void acc_row(float4& acc, uint2 u) {
    float2 f0 = __half22float2(*(__half2*)&u.x);
    float2 f1 = __half22float2(*(__half2*)&u.y);
    acc.x += f0.x; acc.y += f0.y; acc.z += f1.x; acc.w += f1.y;
}

__global__ void aggregate(const __half* __restrict__ x,
                          const int* __restrict__ row_ptr,
                          const int* __restrict__ col,
                          const float* __restrict__ norm_dst,
                          float* __restrict__ agg, int N) {
    int warp = (blockIdx.x * blockDim.x + threadIdx.x) >> 5;
    int lane = threadIdx.x & 31;
    if (warp >= N) return;
    int beg = row_ptr[warp];
    int end = row_ptr[warp + 1];
    float4 acc = make_float4(0.f, 0.f, 0.f, 0.f);
    const __half* xl = x + lane * 4;

    for (int base = beg; base < end; base += 32) {
        int idx = 0;
        if (base + lane < end) idx = __ldg(&col[base + lane]);
        int m = end - base; if (m > 32) m = 32;
        int j = 0;
        for (; j + 8 <= m; j += 8) {
            int s0 = __shfl_sync(0xffffffffu, idx, j + 0);
            int s1 = __shfl_sync(0xffffffffu, idx, j + 1);
            int s2 = __shfl_sync(0xffffffffu, idx, j + 2);
            int s3 = __shfl_sync(0xffffffffu, idx, j + 3);
            int s4 = __shfl_sync(0xffffffffu, idx, j + 4);
            int s5 = __shfl_sync(0xffffffffu, idx, j + 5);
            int s6 = __shfl_sync(0xffffffffu, idx, j + 6);
            int s7 = __shfl_sync(0xffffffffu, idx, j + 7);
            uint2 u0 = *(const uint2*)&xl[(long)s0 * DDIM];
            uint2 u1 = *(const uint2*)&xl[(long)s1 * DDIM];
            uint2 u2 = *(const uint2*)&xl[(long)s2 * DDIM];
            uint2 u3 = *(const uint2*)&xl[(long)s3 * DDIM];
            uint2 u4 = *(const uint2*)&xl[(long)s4 * DDIM];
            uint2 u5 = *(const uint2*)&xl[(long)s5 * DDIM];
            uint2 u6 = *(const uint2*)&xl[(long)s6 * DDIM];
            uint2 u7 = *(const uint2*)&xl[(long)s7 * DDIM];
            acc_row(acc, u0); acc_row(acc, u1); acc_row(acc, u2); acc_row(acc, u3);
            acc_row(acc, u4); acc_row(acc, u5); acc_row(acc, u6); acc_row(acc, u7);
        }
        for (; j < m; j++) {
            int s = __shfl_sync(0xffffffffu, idx, j);
            uint2 u = *(const uint2*)&xl[(long)s * DDIM];
            acc_row(acc, u);
        }
    }
    float nd = norm_dst[warp];
    acc.x *= nd; acc.y *= nd; acc.z *= nd; acc.w *= nd;
    *(float4*)&agg[(long)warp * DDIM + lane * 4] = acc;
}

// ---------------- tensor-core GEMM via mma.sync (split-bf16, fp32 accum) ----------------
// y = A @ Wt^T + b ;  if out_h: out_h = fp16(y * scale[row]) (next-layer input)
//                     else:     out_f = y (final fp32 output)
// CTA tile: 128 rows x 128 cols, 8 warps in 2(row)x4(col), warp tile 64x32.

#define SMG_BIAS  0
#define SMG_A_HI  512
#define SMG_A_LO  (SMG_A_HI + 32768)
#define SMG_W_HI  (SMG_A_LO + 32768)
#define SMG_W_LO  (SMG_W_HI + 128 * 272)
#define SMG_TOTAL (SMG_W_LO + 128 * 272)   // 512 + 65536 + 69632 = 135680

__global__ void __launch_bounds__(256) gemm_mma(
    const float* __restrict__ A,
    const __nv_bfloat16* __restrict__ Wt_hi,
    const __nv_bfloat16* __restrict__ Wt_lo,
    const float* __restrict__ bias,
    const float* __restrict__ scale,   // used only when out_h != nullptr
    __half* __restrict__ out_h,        // fp16 output (layers 0..2)
    float* __restrict__ out_f,         // fp32 output (last layer)
    int N) {
    extern __shared__ char smem[];
    uint32_t sbase = smem_u32(smem);
    int tid = threadIdx.x;
    int wid = tid >> 5;
    int lane = tid & 31;
    int row0 = blockIdx.x * 128;

    // bias -> smem
    if (tid < DDIM) ((float*)(smem + SMG_BIAS))[tid] = bias[tid];

    // ---- stage A tile (128x128 fp32 -> bf16 hi/lo, swizzled) ----
    #pragma unroll
    for (int i = 0; i < 16; i++) {
        int v = tid + i * 256;            // 4096 float4 loads
        int r = v >> 5;                   // row
        int c = (v & 31) * 4;             // col
        int kc = c >> 3;                  // 16B chunk index (8 bf16)
        uint32_t off = (uint32_t)r * 256u + (uint32_t)((kc ^ (r & 7)) * 16) + (uint32_t)((c & 4) * 2);
        int grow = row0 + r;
        float4 f = make_float4(0.f, 0.f, 0.f, 0.f);
        if (grow < N) f = ((const float4*)A)[(long)grow * 32 + (v & 31)];
        __nv_bfloat16 h0 = __float2bfloat16(f.x), h1 = __float2bfloat16(f.y);
        __nv_bfloat16 h2 = __float2bfloat16(f.z), h3 = __float2bfloat16(f.w);
        __nv_bfloat162 hi01 = {h0, h1}, hi23 = {h2, h3};
        __nv_bfloat162 lo01 = {__float2bfloat16(f.x - __bfloat162float(h0)),
                               __float2bfloat16(f.y - __bfloat162float(h1))};
        __nv_bfloat162 lo23 = {__float2bfloat16(f.z - __bfloat162float(h2)),
                               __float2bfloat16(f.w - __bfloat162float(h3))};
        *(__nv_bfloat162*)(smem + SMG_A_HI + off)     = hi01;
        *(__nv_bfloat162*)(smem + SMG_A_HI + off + 4) = hi23;
        *(__nv_bfloat162*)(smem + SMG_A_LO + off)     = lo01;
        *(__nv_bfloat162*)(smem + SMG_A_LO + off + 4) = lo23;
    }
    // ---- stage W tiles (bf16 [n][k] -> smem, row stride 272B) ----
    #pragma unroll
    for (int i = 0; i < 8; i++) {
        int u = tid + i * 256;            // 2048 16B chunks
        int n = u >> 4;
        int kc = u & 15;
        uint32_t doff = (uint32_t)n * 272u + (uint32_t)kc * 16u;
        *(uint4*)(smem + SMG_W_HI + doff) = ((const uint4*)Wt_hi)[u];
        *(uint4*)(smem + SMG_W_LO + doff) = ((const uint4*)Wt_lo)[u];
    }
    __syncthreads();

    // warp tiling: 2 row-warps x 4 col-warps
    int warpRow = (wid & 1) * 64;         // 4 m16 tiles
    int warpCol = (wid >> 1) * 32;        // 4 n8 tiles

    float c[4][4][4];                     // [mt][nt][reg]
    #pragma unroll
    for (int mt = 0; mt < 4; mt++)
        #pragma unroll
        for (int nt = 0; nt < 4; nt++)
            #pragma unroll
            for (int q = 0; q < 4; q++) c[mt][nt][q] = 0.f;

    int a_r_off = lane & 15;              // row within m16 tile
    int a_kc_half = lane >> 4;            // 0/1 -> second k8 chunk

    #pragma unroll
    for (int kch = 0; kch < 8; kch++) {   // 16 k per chunk
        uint32_t a_hi[4][4], a_lo[4][4];
        #pragma unroll
        for (int mt = 0; mt < 4; mt++) {
            int r = warpRow + mt * 16 + a_r_off;
            int kc = kch * 2 + a_kc_half;
            uint32_t off = (uint32_t)r * 256u + (uint32_t)((kc ^ (r & 7)) * 16);
            ldm_x4(a_hi[mt][0], a_hi[mt][1], a_hi[mt][2], a_hi[mt][3], sbase + SMG_A_HI + off);
            ldm_x4(a_lo[mt][0], a_lo[mt][1], a_lo[mt][2], a_lo[mt][3], sbase + SMG_A_LO + off);
        }
        uint32_t b_hi[4][2], b_lo[4][2];
        #pragma unroll
        for (int nt = 0; nt < 4; nt++) {
            int n = warpCol + nt * 8 + (lane >> 2);
            uint32_t base = (uint32_t)n * 272u + (uint32_t)kch * 32u + (uint32_t)((lane & 3) * 4);
            b_hi[nt][0] = *(const uint32_t*)(smem + SMG_W_HI + base);
            b_hi[nt][1] = *(const uint32_t*)(smem + SMG_W_HI + base + 16);
            b_lo[nt][0] = *(const uint32_t*)(smem + SMG_W_LO + base);
            b_lo[nt][1] = *(const uint32_t*)(smem + SMG_W_LO + base + 16);
        }
        #pragma unroll
        for (int mt = 0; mt < 4; mt++)
            #pragma unroll
            for (int nt = 0; nt < 4; nt++) {
                mma_bf16(c[mt][nt][0], c[mt][nt][1], c[mt][nt][2], c[mt][nt][3],
                         a_hi[mt][0], a_hi[mt][1], a_hi[mt][2], a_hi[mt][3],
                         b_hi[nt][0], b_hi[nt][1]);
                mma_bf16(c[mt][nt][0], c[mt][nt][1], c[mt][nt][2], c[mt][nt][3],
                         a_hi[mt][0], a_hi[mt][1], a_hi[mt][2], a_hi[mt][3],
                         b_lo[nt][0], b_lo[nt][1]);
                mma_bf16(c[mt][nt][0], c[mt][nt][1], c[mt][nt][2], c[mt][nt][3],
                         a_lo[mt][0], a_lo[mt][1], a_lo[mt][2], a_lo[mt][3],
                         b_hi[nt][0], b_hi[nt][1]);
            }
    }

    // ---- epilogue ----
    const float* sBias = (const float*)(smem + SMG_BIAS);
    #pragma unroll
    for (int mt = 0; mt < 4; mt++) {
        int r_top = row0 + warpRow + mt * 16 + (lane >> 2);
        int r_bot = r_top + 8;
        float s_top = 1.f, s_bot = 1.f;
        if (out_h) {
            if (r_top < N) s_top = __ldg(&scale[r_top]);
            if (r_bot < N) s_bot = __ldg(&scale[r_bot]);
        }
        #pragma unroll
        for (int nt = 0; nt < 4; nt++) {
            int cn = warpCol + nt * 8 + (lane & 3) * 2;
            float b0 = sBias[cn], b1 = sBias[cn + 1];
            if (out_h) {
                if (r_top < N) {
                    __half2 h = __floats2half2_rn((c[mt][nt][0] + b0) * s_top,
                                                  (c[mt][nt][1] + b1) * s_top);
                    *(__half2*)&out_h[(long)r_top * DDIM + cn] = h;
                }
                if (r_bot < N) {
                    __half2 h = __floats2half2_rn((c[mt][nt][2] + b0) * s_bot,
                                                  (c[mt][nt][3] + b1) * s_bot);
                    *(__half2*)&out_h[(long)r_bot * DDIM + cn] = h;
                }
            } else {
                if (r_top < N) {
                    float2 o = {c[mt][nt][0] + b0, c[mt][nt][1] + b1};
                    *(float2*)&out_f[(long)r_top * DDIM + cn] = o;
                }
                if (r_bot < N) {
                    float2 o = {c[mt][nt][2] + b0, c[mt][nt][3] + b1};
                    *(float2*)&out_f[(long)r_bot * DDIM + cn] = o;
                }
            }
        }
    }
}

// ---------------- launch ----------------
extern "C" void kernel_launch(void* const* d_in, const int* in_sizes, int n_in,
                              void* d_out, int out_size) {
    const float* feat = (const float*)d_in[0];      // [N,128]
    const float* W    = (const float*)d_in[1];      // [4,128,128]
    const float* b    = (const float*)d_in[2];      // [4,128]
    const void*  src  = d_in[3];                    // [E] int32 or int64
    const void*  dst  = d_in[4];                    // [E] int32 or int64
    float* out = (float*)d_out;

    int N = in_sizes[0] / DDIM;
    int E = in_sizes[3];

    float *AGG, *ns, *nd;
    __half* X;
    int *outdeg, *indeg, *rowptr, *cursor, *col;
    __nv_bfloat16 *Wth, *Wtl;
    cudaGetSymbolAddress((void**)&X,      g_X);
    cudaGetSymbolAddress((void**)&AGG,    g_AGG);
    cudaGetSymbolAddress((void**)&ns,     g_ns);
    cudaGetSymbolAddress((void**)&nd,     g_nd);
    cudaGetSymbolAddress((void**)&outdeg, g_outdeg);
    cudaGetSymbolAddress((void**)&indeg,  g_indeg);
    cudaGetSymbolAddress((void**)&rowptr, g_rowptr);
    cudaGetSymbolAddress((void**)&cursor, g_cursor);
    cudaGetSymbolAddress((void**)&col,    g_col);
    cudaGetSymbolAddress((void**)&Wth,    g_Wt_hi);
    cudaGetSymbolAddress((void**)&Wtl,    g_Wt_lo);

    static int smem_set = 0;
    if (!smem_set) {
        cudaFuncSetAttribute(gemm_mma, cudaFuncAttributeMaxDynamicSharedMemorySize, SMG_TOTAL);
        smem_set = 1;
    }

    // 0) detect index dtype; prep W splits
    detect_idx_dtype<<<1, 1>>>((const int*)src, (const int*)dst);
    prep_w<<<NLAYERS, 256>>>(W, Wth, Wtl);

    // 1) degrees + norms
    zero_ints2<<<(N + 255) / 256, 256>>>(outdeg, indeg, N);
    count_deg<<<(E + 255) / 256, 256>>>(src, dst, outdeg, indeg, E);
    compute_norms<<<(N + 255) / 256, 256>>>(outdeg, indeg, ns, nd, N);

    // 2) CSR by dst
    scan_kernel<<<1, 1024>>>(indeg, rowptr, cursor, N);
    fill_csr<<<(E + 255) / 256, 256>>>(src, dst, cursor, col, E);

    // 3) layer-0 input: fp16(feat * norm_src)
    scale_rows<<<(N * 32 + 255) / 256, 256>>>(feat, ns, X, N * 32);

    // 4) layers (norm_src folded into gemm epilogue of layers 0..2)
    int agg_blocks  = (N * 32 + 255) / 256;
    int gemm_blocks = (N + 127) / 128;
    for (int l = 0; l < NLAYERS; l++) {
        aggregate<<<agg_blocks, 256>>>(X, rowptr, col, nd, AGG, N);
        bool last = (l == NLAYERS - 1);
        gemm_mma<<<gemm_blocks, 256, SMG_TOTAL>>>(
            AGG, Wth + (long)l * DDIM * DDIM, Wtl + (long)l * DDIM * DDIM,
            b + (long)l * DDIM, ns,
            last ? nullptr : X, last ? out : nullptr, N);
    }
}